// round 6
// baseline (speedup 1.0000x reference)
#include <cuda_runtime.h>
#include <math.h>

#define Bsz    4
#define Cdim   128
#define Lseq   4096
#define Dd     32
#define DI     64
#define DS     16
#define NPROJ  34
#define SEQ    16
#define NC     256
#define TC     16
#define TILE   32
#define EPSf   1e-5f

// ---------------- scratch (device globals) ----------------
__device__ float g_xn2[SEQ*Lseq*Dd];     // post double-LN
__device__ float g_xc [SEQ*Lseq*DI];     // conv+silu output
__device__ float g_z  [SEQ*Lseq*DI];     // gate branch
__device__ float g_bc [SEQ*Lseq*32];     // B(16)|C(16) per token
__device__ float g_dt [SEQ*Lseq*DI];     // softplus dt
__device__ float g_P  [SEQ*NC*DI*DS];    // chunk A-products
__device__ float g_Q  [SEQ*NC*DI*DS];    // chunk local scans
__device__ float g_hin[SEQ*NC*DI*DS];    // chunk initial states
__device__ float g_ym [SEQ*Lseq*DI];     // gated scan output
__device__ float g_zc [Bsz*Lseq*Cdim];   // concatenated split outputs
__device__ float g_pwt[Cdim*Cdim];       // transposed final proj weight

__device__ __forceinline__ float wsum(float v){
    #pragma unroll
    for(int o=16;o;o>>=1) v += __shfl_xor_sync(0xffffffffu, v, o);
    return v;
}
__device__ __forceinline__ float siluf(float x){ return x/(1.f+__expf(-x)); }

// ---------------- K0: transpose final projection weight ----------------
__global__ void k_tr(const float* __restrict__ pw){
    int i = blockIdx.x*256 + threadIdx.x;      // 16384
    int o = i>>7, c = i&127;
    g_pwt[c*128+o] = pw[i];
}

// ---------------- K1: LN over C, then per-split LN over D ----------------
__global__ void k_ln(const float* __restrict__ x, const float* __restrict__ lg,
                     const float* __restrict__ lb, const float* __restrict__ pg,
                     const float* __restrict__ pb){
    __shared__ float sx[128][33];
    int b = blockIdx.y, l0 = blockIdx.x*32, tid = threadIdx.x;
    for(int i=tid;i<128*32;i+=256){
        int c=i>>5, li=i&31;
        sx[c][li] = x[(b*128 + c)*Lseq + l0 + li];
    }
    __syncthreads();
    int w = tid>>5, lane = tid&31;
    for(int lc=w; lc<32; lc+=8){
        float v0=sx[lane][lc], v1=sx[lane+32][lc], v2=sx[lane+64][lc], v3=sx[lane+96][lc];
        float mu = wsum(v0+v1+v2+v3)*(1.f/128.f);
        float d0=v0-mu,d1=v1-mu,d2=v2-mu,d3=v3-mu;
        float rs = rsqrtf(wsum(d0*d0+d1*d1+d2*d2+d3*d3)*(1.f/128.f)+EPSf);
        float xn[4];
        xn[0]=d0*rs*lg[lane     ]+lb[lane     ];
        xn[1]=d1*rs*lg[lane+ 32]+lb[lane+ 32];
        xn[2]=d2*rs*lg[lane+ 64]+lb[lane+ 64];
        xn[3]=d3*rs*lg[lane+ 96]+lb[lane+ 96];
        #pragma unroll
        for(int g=0; g<4; g++){
            float mu2 = wsum(xn[g])*(1.f/32.f);
            float dd  = xn[g]-mu2;
            float rs2 = rsqrtf(wsum(dd*dd)*(1.f/32.f)+EPSf);
            float o = dd*rs2*pg[g*32+lane] + pb[g*32+lane];
            g_xn2[((g*Bsz + b)*Lseq + l0+lc)*Dd + lane] = o;
        }
    }
}

// ---- K2: fused in_proj + causal conv + SiLU + x_proj + dt (32-token tile, 3 halo) ----
__global__ void k_fused(const float* __restrict__ Win, const float* __restrict__ cw,
                        const float* __restrict__ cb,  const float* __restrict__ Wx,
                        const float* __restrict__ dtw, const float* __restrict__ dtb){
    __shared__ float sxz[35*128];      // xz for 35 tokens (halo 3)
    __shared__ float sxc[32*64];       // conv+silu result
    __shared__ float sbuf[2176];       // sxn (35*32), later sWx (64*34)
    __shared__ float sdtr[64];         // dt-rank projections (32 tokens x 2)
    int seq=blockIdx.y, g=seq>>2, tid=threadIdx.x;
    int l0 = blockIdx.x*TILE;

    float w[32];
    #pragma unroll
    for(int k=0;k<32;k++) w[k] = Win[g*4096 + k*128 + tid];

    for(int i=tid;i<35*32;i+=128){
        int j=i>>5, k=i&31, tt=l0-3+j;
        sbuf[i] = (tt>=0)? g_xn2[(seq*Lseq+tt)*32 + k] : 0.f;
    }
    __syncthreads();

    #pragma unroll 5
    for(int j=0;j<35;j++){
        float acc=0.f;
        #pragma unroll
        for(int k=0;k<32;k+=4){
            float4 v = *(const float4*)&sbuf[j*32+k];
            acc = fmaf(v.x,w[k  ],acc); acc = fmaf(v.y,w[k+1],acc);
            acc = fmaf(v.z,w[k+2],acc); acc = fmaf(v.w,w[k+3],acc);
        }
        sxz[j*128+tid]=acc;
    }
    __syncthreads();

    for(int i=tid;i<64*NPROJ;i+=128) sbuf[i] = Wx[g*64*NPROJ + i];

    {
        int ch = tid&63;
        float c0=cw[g*256+ch*4], c1=cw[g*256+ch*4+1], c2=cw[g*256+ch*4+2], c3=cw[g*256+ch*4+3];
        float bb=cb[g*64+ch];
        for(int t = tid>>6; t<32; t+=2){
            float acc = bb;
            acc = fmaf(sxz[ t   *128+ch], c0, acc);
            acc = fmaf(sxz[(t+1)*128+ch], c1, acc);
            acc = fmaf(sxz[(t+2)*128+ch], c2, acc);
            acc = fmaf(sxz[(t+3)*128+ch], c3, acc);
            float v = siluf(acc);
            sxc[t*64+ch] = v;
            g_xc[(seq*Lseq+l0+t)*64+ch] = v;
            g_z [(seq*Lseq+l0+t)*64+ch] = sxz[(t+3)*128 + 64 + ch];
        }
    }
    __syncthreads();

    for(int i=tid;i<32*NPROJ;i+=128){
        int t=i/NPROJ, n=i-t*NPROJ;
        float acc=0.f;
        #pragma unroll 8
        for(int k=0;k<64;k++) acc = fmaf(sxc[t*64+k], sbuf[k*NPROJ+n], acc);
        if(n<2) sdtr[t*2+n]=acc;
        else    g_bc[(seq*Lseq+l0+t)*32 + n-2]=acc;
    }
    __syncthreads();

    {
        int d = tid&63;
        float w0 = dtw[g*128+d], w1 = dtw[g*128+64+d], bb=dtb[g*64+d];
        for(int t=tid>>6;t<32;t+=2){
            float v = fmaf(sdtr[t*2],w0,fmaf(sdtr[t*2+1],w1,bb));
            g_dt[(seq*Lseq+l0+t)*64+d] = (v>20.f)? v : log1pf(__expf(v));
        }
    }
}

// ---------------- K3: scan phase 1 — per-chunk (P, Q) ----------------
// 256 threads = 4 chunks; no smem; coalesced dt/xc, uniform float4 B loads.
// P[s] = exp(A[s]*sum(dt)) computed once per chunk.
__global__ void k_scan1(const float* __restrict__ A_log){
    int seq=blockIdx.y, g=seq>>2;
    int sub=threadIdx.x>>6, d=threadIdx.x&63;
    int ck=blockIdx.x*4+sub;
    float A[DS], Q[DS];
    #pragma unroll
    for(int s=0;s<DS;s++){ A[s] = -__expf(A_log[(g*64+d)*16+s]); Q[s]=0.f; }
    int tb = ck*TC;
    const float* __restrict__ dtp = &g_dt[(seq*Lseq+tb)*64 + d];
    const float* __restrict__ xcp = &g_xc[(seq*Lseq+tb)*64 + d];
    const float* __restrict__ bcp = &g_bc[(seq*Lseq+tb)*32];
    float sdt = 0.f;
    #pragma unroll 4
    for(int t=0;t<TC;t++){
        float dtv = dtp[t*64];
        float dx  = dtv * xcp[t*64];
        sdt += dtv;
        float4 b0 = *(const float4*)&bcp[t*32];
        float4 b1 = *(const float4*)&bcp[t*32+4];
        float4 b2 = *(const float4*)&bcp[t*32+8];
        float4 b3 = *(const float4*)&bcp[t*32+12];
        float bb[16]={b0.x,b0.y,b0.z,b0.w,b1.x,b1.y,b1.z,b1.w,
                      b2.x,b2.y,b2.z,b2.w,b3.x,b3.y,b3.z,b3.w};
        #pragma unroll
        for(int s=0;s<DS;s++){
            float e = __expf(A[s]*dtv);
            Q[s] = fmaf(e, Q[s], dx*bb[s]);
        }
    }
    int base = ((seq*NC+ck)*64 + d)*16;
    #pragma unroll
    for(int s=0;s<16;s+=4){
        float4 p;
        p.x = __expf(A[s  ]*sdt);
        p.y = __expf(A[s+1]*sdt);
        p.z = __expf(A[s+2]*sdt);
        p.w = __expf(A[s+3]*sdt);
        *(float4*)&g_P[base+s] = p;
        *(float4*)&g_Q[base+s] = make_float4(Q[s],Q[s+1],Q[s+2],Q[s+3]);
    }
}

// ---------------- K4: scan phase 2 — sequential across chunks ----------------
__global__ void k_scan2(){
    int idx = blockIdx.x*128 + threadIdx.x;     // SEQ*1024 = 16384
    int lane = idx & 1023; int seq = idx >> 10;
    float h = 0.f;
    int base = seq*NC*1024 + lane;
    #pragma unroll 8
    for(int c=0;c<NC;c++){
        g_hin[base + c*1024] = h;
        h = fmaf(g_P[base + c*1024], h, g_Q[base + c*1024]);
    }
}

// ---------------- K5: scan phase 3 — replay + y + gate fusion ----------------
__global__ void k_scan3(const float* __restrict__ A_log, const float* __restrict__ Dpar){
    int seq=blockIdx.y, g=seq>>2;
    int sub=threadIdx.x>>6, d=threadIdx.x&63;
    int ck=blockIdx.x*4+sub;
    float A[DS], h[DS];
    #pragma unroll
    for(int s=0;s<DS;s++) A[s] = -__expf(A_log[(g*64+d)*16+s]);
    int hb = ((seq*NC+ck)*64 + d)*16;
    #pragma unroll
    for(int s=0;s<16;s+=4){
        float4 v = *(const float4*)&g_hin[hb+s];
        h[s]=v.x; h[s+1]=v.y; h[s+2]=v.z; h[s+3]=v.w;
    }
    float Dp = Dpar[g*64+d];
    int tb = ck*TC;
    const float* __restrict__ dtp = &g_dt[(seq*Lseq+tb)*64 + d];
    const float* __restrict__ xcp = &g_xc[(seq*Lseq+tb)*64 + d];
    const float* __restrict__ zp  = &g_z [(seq*Lseq+tb)*64 + d];
    const float* __restrict__ bcp = &g_bc[(seq*Lseq+tb)*32];
    float*       __restrict__ ymp = &g_ym[(seq*Lseq+tb)*64 + d];
    #pragma unroll 4
    for(int t=0;t<TC;t++){
        float dtv = dtp[t*64];
        float xcv = xcp[t*64];
        float dx  = dtv*xcv;
        float4 b0 = *(const float4*)&bcp[t*32];
        float4 b1 = *(const float4*)&bcp[t*32+4];
        float4 b2 = *(const float4*)&bcp[t*32+8];
        float4 b3 = *(const float4*)&bcp[t*32+12];
        float4 c0 = *(const float4*)&bcp[t*32+16];
        float4 c1 = *(const float4*)&bcp[t*32+20];
        float4 c2 = *(const float4*)&bcp[t*32+24];
        float4 c3 = *(const float4*)&bcp[t*32+28];
        float bb[16]={b0.x,b0.y,b0.z,b0.w,b1.x,b1.y,b1.z,b1.w,
                      b2.x,b2.y,b2.z,b2.w,b3.x,b3.y,b3.z,b3.w};
        float cc[16]={c0.x,c0.y,c0.z,c0.w,c1.x,c1.y,c1.z,c1.w,
                      c2.x,c2.y,c2.z,c2.w,c3.x,c3.y,c3.z,c3.w};
        float y = 0.f;
        #pragma unroll
        for(int s=0;s<DS;s++){
            float e = __expf(A[s]*dtv);
            h[s] = fmaf(e, h[s], dx*bb[s]);
            y = fmaf(h[s], cc[s], y);
        }
        ymp[t*64] = (y + Dp*xcv) * siluf(zp[t*64]);
    }
}

// ---------------- K6: out_proj(64->32) + skip + pvm_proj(32->32) ----------------
__global__ void k_out(const float* __restrict__ W1, const float* __restrict__ W2,
                      const float* __restrict__ pb2, const float* __restrict__ skipv){
    __shared__ float sW1[64*32], sW2[32*32], spb[32], su[8*32], sym[8*64];
    int seq=blockIdx.y, g=seq>>2, b=seq&3, t0=blockIdx.x*8, tid=threadIdx.x;
    for(int i=tid;i<2048;i+=256) sW1[i]=W1[g*2048+i];
    for(int i=tid;i<1024;i+=256) sW2[i]=W2[g*1024+i];
    if(tid<32) spb[tid]=pb2[g*32+tid];
    for(int i=tid;i<512;i+=256) sym[i]=g_ym[(seq*Lseq+t0)*64 + i];
    float skip = skipv[g];
    __syncthreads();
    int w = tid>>5, lane = tid&31;
    int t = t0 + w;
    float acc = 0.f;
    #pragma unroll 8
    for(int k=0;k<64;k++) acc = fmaf(sym[w*64+k], sW1[k*32+lane], acc);
    float u = acc + skip * g_xn2[(seq*Lseq+t)*32 + lane];
    su[w*32+lane] = u;
    __syncwarp();
    float acc2 = spb[lane];
    #pragma unroll 8
    for(int n=0;n<32;n++) acc2 = fmaf(su[w*32+n], sW2[n*32+lane], acc2);
    g_zc[(b*Lseq+t)*128 + g*32 + lane] = acc2;
}

// ---------------- K7: final proj (128x128) + BN + exact GELU ----------------
__global__ void k_final(const float* __restrict__ pb2, const float* __restrict__ bg,
                        const float* __restrict__ bb, const float* __restrict__ bm,
                        const float* __restrict__ bv, float* __restrict__ out){
    __shared__ float st[32*128];
    int b = blockIdx.y, l0 = blockIdx.x*32, o = threadIdx.x;
    for(int i=o;i<4096;i+=128) st[i] = g_zc[(b*Lseq+l0)*128 + i];
    float scale = bg[o]*rsqrtf(bv[o]+EPSf);
    float c0 = (pb2[o]-bm[o])*scale + bb[o];
    __syncthreads();
    float acc[32];
    #pragma unroll
    for(int t=0;t<32;t++) acc[t]=0.f;
    #pragma unroll 4
    for(int c=0;c<128;c++){
        float w = g_pwt[c*128+o];
        #pragma unroll
        for(int t=0;t<32;t++) acc[t] = fmaf(st[t*128+c], w, acc[t]);
    }
    __syncthreads();
    #pragma unroll
    for(int t=0;t<32;t++){
        float v = fmaf(acc[t], scale, c0);
        st[o*32+t] = 0.5f*v*(1.f + erff(v*0.70710678118654752f));
    }
    __syncthreads();
    for(int i=o;i<4096;i+=128){
        int oo = i>>5, li = i&31;
        out[(b*128+oo)*Lseq + l0 + li] = st[i];
    }
}

// ---------------- launch ----------------
extern "C" void kernel_launch(void* const* d_in, const int* in_sizes, int n_in,
                              void* d_out, int out_size){
    const float* x         = (const float*)d_in[0];
    const float* ln_g      = (const float*)d_in[1];
    const float* ln_b      = (const float*)d_in[2];
    const float* pvm_ln_g  = (const float*)d_in[3];
    const float* pvm_ln_b  = (const float*)d_in[4];
    const float* in_proj_w = (const float*)d_in[5];
    const float* conv_w    = (const float*)d_in[6];
    const float* conv_b    = (const float*)d_in[7];
    const float* x_proj_w  = (const float*)d_in[8];
    const float* dt_proj_w = (const float*)d_in[9];
    const float* dt_bias   = (const float*)d_in[10];
    const float* A_log     = (const float*)d_in[11];
    const float* D_param   = (const float*)d_in[12];
    const float* out_proj_w= (const float*)d_in[13];
    const float* skip_scale= (const float*)d_in[14];
    const float* pvm_proj_w= (const float*)d_in[15];
    const float* pvm_proj_b= (const float*)d_in[16];
    const float* proj_w    = (const float*)d_in[17];
    const float* proj_b    = (const float*)d_in[18];
    const float* bn_g      = (const float*)d_in[19];
    const float* bn_b      = (const float*)d_in[20];
    const float* bn_mean   = (const float*)d_in[21];
    const float* bn_var    = (const float*)d_in[22];
    float* out = (float*)d_out;

    k_tr    <<<64, 256>>>(proj_w);
    k_ln    <<<dim3(128,4), 256>>>(x, ln_g, ln_b, pvm_ln_g, pvm_ln_b);
    k_fused <<<dim3(Lseq/TILE,16), 128>>>(in_proj_w, conv_w, conv_b, x_proj_w, dt_proj_w, dt_bias);
    k_scan1 <<<dim3(NC/4,16), 256>>>(A_log);
    k_scan2 <<<128, 128>>>();
    k_scan3 <<<dim3(NC/4,16), 256>>>(A_log, D_param);
    k_out   <<<dim3(512,16), 256>>>(out_proj_w, pvm_proj_w, pvm_proj_b, skip_scale);
    k_final <<<dim3(128,4), 128>>>(proj_b, bn_g, bn_b, bn_mean, bn_var, out);
}

// round 7
// speedup vs baseline: 1.0327x; 1.0327x over previous
#include <cuda_runtime.h>
#include <math.h>

#define Bsz    4
#define Cdim   128
#define Lseq   4096
#define Dd     32
#define DI     64
#define DS     16
#define NPROJ  34
#define SEQ    16
#define NC     256
#define TC     16
#define TILE   32
#define EPSf   1e-5f

// ---------------- scratch (device globals) ----------------
__device__ float g_xn2[SEQ*Lseq*Dd];     // post double-LN
__device__ float g_xc [SEQ*Lseq*DI];     // conv+silu output
__device__ float g_z  [SEQ*Lseq*DI];     // gate branch
__device__ float g_bc [SEQ*Lseq*32];     // B(16)|C(16) per token
__device__ float g_dt [SEQ*Lseq*DI];     // softplus dt
__device__ float g_P  [SEQ*NC*DI*DS];    // chunk A-products
__device__ float g_Q  [SEQ*NC*DI*DS];    // chunk local scans
__device__ float g_hin[SEQ*NC*DI*DS];    // chunk initial states
__device__ float g_ym [SEQ*Lseq*DI];     // gated scan output
__device__ float g_zc [Bsz*Lseq*Cdim];   // concatenated split outputs
__device__ float g_pwt[Cdim*Cdim];       // transposed final proj weight

__device__ __forceinline__ float wsum(float v){
    #pragma unroll
    for(int o=16;o;o>>=1) v += __shfl_xor_sync(0xffffffffu, v, o);
    return v;
}
__device__ __forceinline__ float siluf(float x){ return x/(1.f+__expf(-x)); }

// ---------------- K0: transpose final projection weight ----------------
__global__ void k_tr(const float* __restrict__ pw){
    int i = blockIdx.x*256 + threadIdx.x;      // 16384
    int o = i>>7, c = i&127;
    g_pwt[c*128+o] = pw[i];
}

// ---------------- K1: LN over C, then per-split LN over D ----------------
__global__ void k_ln(const float* __restrict__ x, const float* __restrict__ lg,
                     const float* __restrict__ lb, const float* __restrict__ pg,
                     const float* __restrict__ pb){
    __shared__ float sx[128][33];
    int b = blockIdx.y, l0 = blockIdx.x*32, tid = threadIdx.x;
    for(int i=tid;i<128*32;i+=256){
        int c=i>>5, li=i&31;
        sx[c][li] = x[(b*128 + c)*Lseq + l0 + li];
    }
    __syncthreads();
    int w = tid>>5, lane = tid&31;
    for(int lc=w; lc<32; lc+=8){
        float v0=sx[lane][lc], v1=sx[lane+32][lc], v2=sx[lane+64][lc], v3=sx[lane+96][lc];
        float mu = wsum(v0+v1+v2+v3)*(1.f/128.f);
        float d0=v0-mu,d1=v1-mu,d2=v2-mu,d3=v3-mu;
        float rs = rsqrtf(wsum(d0*d0+d1*d1+d2*d2+d3*d3)*(1.f/128.f)+EPSf);
        float xn[4];
        xn[0]=d0*rs*lg[lane     ]+lb[lane     ];
        xn[1]=d1*rs*lg[lane+ 32]+lb[lane+ 32];
        xn[2]=d2*rs*lg[lane+ 64]+lb[lane+ 64];
        xn[3]=d3*rs*lg[lane+ 96]+lb[lane+ 96];
        #pragma unroll
        for(int g=0; g<4; g++){
            float mu2 = wsum(xn[g])*(1.f/32.f);
            float dd  = xn[g]-mu2;
            float rs2 = rsqrtf(wsum(dd*dd)*(1.f/32.f)+EPSf);
            float o = dd*rs2*pg[g*32+lane] + pb[g*32+lane];
            g_xn2[((g*Bsz + b)*Lseq + l0+lc)*Dd + lane] = o;
        }
    }
}

// ---- K2: fused in_proj + causal conv + SiLU + x_proj + dt (32-token tile, 3 halo) ----
__global__ void k_fused(const float* __restrict__ Win, const float* __restrict__ cw,
                        const float* __restrict__ cb,  const float* __restrict__ Wx,
                        const float* __restrict__ dtw, const float* __restrict__ dtb){
    __shared__ float sxz[35*128];      // xz for 35 tokens (halo 3)
    __shared__ float sxc[32*64];       // conv+silu result
    __shared__ float sbuf[2176];       // sxn (35*32), later sWx (64*34)
    __shared__ float sdtr[64];         // dt-rank projections (32 tokens x 2)
    int seq=blockIdx.y, g=seq>>2, tid=threadIdx.x;
    int l0 = blockIdx.x*TILE;

    float w[32];
    #pragma unroll
    for(int k=0;k<32;k++) w[k] = Win[g*4096 + k*128 + tid];

    for(int i=tid;i<35*32;i+=128){
        int j=i>>5, k=i&31, tt=l0-3+j;
        sbuf[i] = (tt>=0)? g_xn2[(seq*Lseq+tt)*32 + k] : 0.f;
    }
    __syncthreads();

    #pragma unroll 5
    for(int j=0;j<35;j++){
        float acc=0.f;
        #pragma unroll
        for(int k=0;k<32;k+=4){
            float4 v = *(const float4*)&sbuf[j*32+k];
            acc = fmaf(v.x,w[k  ],acc); acc = fmaf(v.y,w[k+1],acc);
            acc = fmaf(v.z,w[k+2],acc); acc = fmaf(v.w,w[k+3],acc);
        }
        sxz[j*128+tid]=acc;
    }
    __syncthreads();

    for(int i=tid;i<64*NPROJ;i+=128) sbuf[i] = Wx[g*64*NPROJ + i];

    {
        int ch = tid&63;
        float c0=cw[g*256+ch*4], c1=cw[g*256+ch*4+1], c2=cw[g*256+ch*4+2], c3=cw[g*256+ch*4+3];
        float bb=cb[g*64+ch];
        for(int t = tid>>6; t<32; t+=2){
            float acc = bb;
            acc = fmaf(sxz[ t   *128+ch], c0, acc);
            acc = fmaf(sxz[(t+1)*128+ch], c1, acc);
            acc = fmaf(sxz[(t+2)*128+ch], c2, acc);
            acc = fmaf(sxz[(t+3)*128+ch], c3, acc);
            float v = siluf(acc);
            sxc[t*64+ch] = v;
            g_xc[(seq*Lseq+l0+t)*64+ch] = v;
            g_z [(seq*Lseq+l0+t)*64+ch] = sxz[(t+3)*128 + 64 + ch];
        }
    }
    __syncthreads();

    for(int i=tid;i<32*NPROJ;i+=128){
        int t=i/NPROJ, n=i-t*NPROJ;
        float acc=0.f;
        #pragma unroll 8
        for(int k=0;k<64;k++) acc = fmaf(sxc[t*64+k], sbuf[k*NPROJ+n], acc);
        if(n<2) sdtr[t*2+n]=acc;
        else    g_bc[(seq*Lseq+l0+t)*32 + n-2]=acc;
    }
    __syncthreads();

    {
        int d = tid&63;
        float w0 = dtw[g*128+d], w1 = dtw[g*128+64+d], bb=dtb[g*64+d];
        for(int t=tid>>6;t<32;t+=2){
            float v = fmaf(sdtr[t*2],w0,fmaf(sdtr[t*2+1],w1,bb));
            g_dt[(seq*Lseq+l0+t)*64+d] = (v>20.f)? v : log1pf(__expf(v));
        }
    }
}

// ---------------- K3: scan phase 1 — per-chunk (P, Q) ----------------
// 256 threads = 4 chunks; no smem; coalesced dt/xc, uniform float4 B loads.
// P[s] = exp(A[s]*sum(dt)) computed once per chunk.
__global__ void k_scan1(const float* __restrict__ A_log){
    int seq=blockIdx.y, g=seq>>2;
    int sub=threadIdx.x>>6, d=threadIdx.x&63;
    int ck=blockIdx.x*4+sub;
    float A[DS], Q[DS];
    #pragma unroll
    for(int s=0;s<DS;s++){ A[s] = -__expf(A_log[(g*64+d)*16+s]); Q[s]=0.f; }
    int tb = ck*TC;
    const float* __restrict__ dtp = &g_dt[(seq*Lseq+tb)*64 + d];
    const float* __restrict__ xcp = &g_xc[(seq*Lseq+tb)*64 + d];
    const float* __restrict__ bcp = &g_bc[(seq*Lseq+tb)*32];
    float sdt = 0.f;
    #pragma unroll 4
    for(int t=0;t<TC;t++){
        float dtv = dtp[t*64];
        float dx  = dtv * xcp[t*64];
        sdt += dtv;
        float4 b0 = *(const float4*)&bcp[t*32];
        float4 b1 = *(const float4*)&bcp[t*32+4];
        float4 b2 = *(const float4*)&bcp[t*32+8];
        float4 b3 = *(const float4*)&bcp[t*32+12];
        float bb[16]={b0.x,b0.y,b0.z,b0.w,b1.x,b1.y,b1.z,b1.w,
                      b2.x,b2.y,b2.z,b2.w,b3.x,b3.y,b3.z,b3.w};
        #pragma unroll
        for(int s=0;s<DS;s++){
            float e = __expf(A[s]*dtv);
            Q[s] = fmaf(e, Q[s], dx*bb[s]);
        }
    }
    int base = ((seq*NC+ck)*64 + d)*16;
    #pragma unroll
    for(int s=0;s<16;s+=4){
        float4 p;
        p.x = __expf(A[s  ]*sdt);
        p.y = __expf(A[s+1]*sdt);
        p.z = __expf(A[s+2]*sdt);
        p.w = __expf(A[s+3]*sdt);
        *(float4*)&g_P[base+s] = p;
        *(float4*)&g_Q[base+s] = make_float4(Q[s],Q[s+1],Q[s+2],Q[s+3]);
    }
}

// ---------------- K4: scan phase 2 — sequential across chunks ----------------
__global__ void k_scan2(){
    int idx = blockIdx.x*128 + threadIdx.x;     // SEQ*1024 = 16384
    int lane = idx & 1023; int seq = idx >> 10;
    float h = 0.f;
    int base = seq*NC*1024 + lane;
    #pragma unroll 8
    for(int c=0;c<NC;c++){
        g_hin[base + c*1024] = h;
        h = fmaf(g_P[base + c*1024], h, g_Q[base + c*1024]);
    }
}

// ---------------- K5: scan phase 3 — replay + y + gate fusion ----------------
__global__ void k_scan3(const float* __restrict__ A_log, const float* __restrict__ Dpar){
    int seq=blockIdx.y, g=seq>>2;
    int sub=threadIdx.x>>6, d=threadIdx.x&63;
    int ck=blockIdx.x*4+sub;
    float A[DS], h[DS];
    #pragma unroll
    for(int s=0;s<DS;s++) A[s] = -__expf(A_log[(g*64+d)*16+s]);
    int hb = ((seq*NC+ck)*64 + d)*16;
    #pragma unroll
    for(int s=0;s<16;s+=4){
        float4 v = *(const float4*)&g_hin[hb+s];
        h[s]=v.x; h[s+1]=v.y; h[s+2]=v.z; h[s+3]=v.w;
    }
    float Dp = Dpar[g*64+d];
    int tb = ck*TC;
    const float* __restrict__ dtp = &g_dt[(seq*Lseq+tb)*64 + d];
    const float* __restrict__ xcp = &g_xc[(seq*Lseq+tb)*64 + d];
    const float* __restrict__ zp  = &g_z [(seq*Lseq+tb)*64 + d];
    const float* __restrict__ bcp = &g_bc[(seq*Lseq+tb)*32];
    float*       __restrict__ ymp = &g_ym[(seq*Lseq+tb)*64 + d];
    #pragma unroll 4
    for(int t=0;t<TC;t++){
        float dtv = dtp[t*64];
        float xcv = xcp[t*64];
        float dx  = dtv*xcv;
        float4 b0 = *(const float4*)&bcp[t*32];
        float4 b1 = *(const float4*)&bcp[t*32+4];
        float4 b2 = *(const float4*)&bcp[t*32+8];
        float4 b3 = *(const float4*)&bcp[t*32+12];
        float4 c0 = *(const float4*)&bcp[t*32+16];
        float4 c1 = *(const float4*)&bcp[t*32+20];
        float4 c2 = *(const float4*)&bcp[t*32+24];
        float4 c3 = *(const float4*)&bcp[t*32+28];
        float bb[16]={b0.x,b0.y,b0.z,b0.w,b1.x,b1.y,b1.z,b1.w,
                      b2.x,b2.y,b2.z,b2.w,b3.x,b3.y,b3.z,b3.w};
        float cc[16]={c0.x,c0.y,c0.z,c0.w,c1.x,c1.y,c1.z,c1.w,
                      c2.x,c2.y,c2.z,c2.w,c3.x,c3.y,c3.z,c3.w};
        float y = 0.f;
        #pragma unroll
        for(int s=0;s<DS;s++){
            float e = __expf(A[s]*dtv);
            h[s] = fmaf(e, h[s], dx*bb[s]);
            y = fmaf(h[s], cc[s], y);
        }
        ymp[t*64] = (y + Dp*xcv) * siluf(zp[t*64]);
    }
}

// ---------------- K6: out_proj(64->32) + skip + pvm_proj(32->32) ----------------
__global__ void k_out(const float* __restrict__ W1, const float* __restrict__ W2,
                      const float* __restrict__ pb2, const float* __restrict__ skipv){
    __shared__ float sW1[64*32], sW2[32*32], spb[32], su[8*32], sym[8*64];
    int seq=blockIdx.y, g=seq>>2, b=seq&3, t0=blockIdx.x*8, tid=threadIdx.x;
    for(int i=tid;i<2048;i+=256) sW1[i]=W1[g*2048+i];
    for(int i=tid;i<1024;i+=256) sW2[i]=W2[g*1024+i];
    if(tid<32) spb[tid]=pb2[g*32+tid];
    for(int i=tid;i<512;i+=256) sym[i]=g_ym[(seq*Lseq+t0)*64 + i];
    float skip = skipv[g];
    __syncthreads();
    int w = tid>>5, lane = tid&31;
    int t = t0 + w;
    float acc = 0.f;
    #pragma unroll 8
    for(int k=0;k<64;k++) acc = fmaf(sym[w*64+k], sW1[k*32+lane], acc);
    float u = acc + skip * g_xn2[(seq*Lseq+t)*32 + lane];
    su[w*32+lane] = u;
    __syncwarp();
    float acc2 = spb[lane];
    #pragma unroll 8
    for(int n=0;n<32;n++) acc2 = fmaf(su[w*32+n], sW2[n*32+lane], acc2);
    g_zc[(b*Lseq+t)*128 + g*32 + lane] = acc2;
}

// ---------------- K7: final proj (128x128) + BN + exact GELU ----------------
__global__ void k_final(const float* __restrict__ pb2, const float* __restrict__ bg,
                        const float* __restrict__ bb, const float* __restrict__ bm,
                        const float* __restrict__ bv, float* __restrict__ out){
    __shared__ float st[32*128];
    int b = blockIdx.y, l0 = blockIdx.x*32, o = threadIdx.x;
    for(int i=o;i<4096;i+=128) st[i] = g_zc[(b*Lseq+l0)*128 + i];
    float scale = bg[o]*rsqrtf(bv[o]+EPSf);
    float c0 = (pb2[o]-bm[o])*scale + bb[o];
    __syncthreads();
    float acc[32];
    #pragma unroll
    for(int t=0;t<32;t++) acc[t]=0.f;
    #pragma unroll 4
    for(int c=0;c<128;c++){
        float w = g_pwt[c*128+o];
        #pragma unroll
        for(int t=0;t<32;t++) acc[t] = fmaf(st[t*128+c], w, acc[t]);
    }
    __syncthreads();
    #pragma unroll
    for(int t=0;t<32;t++){
        float v = fmaf(acc[t], scale, c0);
        st[o*32+t] = 0.5f*v*(1.f + erff(v*0.70710678118654752f));
    }
    __syncthreads();
    for(int i=o;i<4096;i+=128){
        int oo = i>>5, li = i&31;
        out[(b*128+oo)*Lseq + l0 + li] = st[i];
    }
}

// ---------------- launch ----------------
extern "C" void kernel_launch(void* const* d_in, const int* in_sizes, int n_in,
                              void* d_out, int out_size){
    const float* x         = (const float*)d_in[0];
    const float* ln_g      = (const float*)d_in[1];
    const float* ln_b      = (const float*)d_in[2];
    const float* pvm_ln_g  = (const float*)d_in[3];
    const float* pvm_ln_b  = (const float*)d_in[4];
    const float* in_proj_w = (const float*)d_in[5];
    const float* conv_w    = (const float*)d_in[6];
    const float* conv_b    = (const float*)d_in[7];
    const float* x_proj_w  = (const float*)d_in[8];
    const float* dt_proj_w = (const float*)d_in[9];
    const float* dt_bias   = (const float*)d_in[10];
    const float* A_log     = (const float*)d_in[11];
    const float* D_param   = (const float*)d_in[12];
    const float* out_proj_w= (const float*)d_in[13];
    const float* skip_scale= (const float*)d_in[14];
    const float* pvm_proj_w= (const float*)d_in[15];
    const float* pvm_proj_b= (const float*)d_in[16];
    const float* proj_w    = (const float*)d_in[17];
    const float* proj_b    = (const float*)d_in[18];
    const float* bn_g      = (const float*)d_in[19];
    const float* bn_b      = (const float*)d_in[20];
    const float* bn_mean   = (const float*)d_in[21];
    const float* bn_var    = (const float*)d_in[22];
    float* out = (float*)d_out;

    k_tr    <<<64, 256>>>(proj_w);
    k_ln    <<<dim3(128,4), 256>>>(x, ln_g, ln_b, pvm_ln_g, pvm_ln_b);
    k_fused <<<dim3(Lseq/TILE,16), 128>>>(in_proj_w, conv_w, conv_b, x_proj_w, dt_proj_w, dt_bias);
    k_scan1 <<<dim3(NC/4,16), 256>>>(A_log);
    k_scan2 <<<128, 128>>>();
    k_scan3 <<<dim3(NC/4,16), 256>>>(A_log, D_param);
    k_out   <<<dim3(512,16), 256>>>(out_proj_w, pvm_proj_w, pvm_proj_b, skip_scale);
    k_final <<<dim3(128,4), 128>>>(proj_b, bn_g, bn_b, bn_mean, bn_var, out);
}

// round 8
// speedup vs baseline: 1.0335x; 1.0007x over previous
#include <cuda_runtime.h>
#include <math.h>

#define Bsz    4
#define Cdim   128
#define Lseq   4096
#define Dd     32
#define DI     64
#define DS     16
#define NPROJ  34
#define SEQ    16
#define NC     256
#define TC     16
#define TILE   32
#define EPSf   1e-5f

// ---------------- scratch (device globals) ----------------
__device__ float g_xn2[SEQ*Lseq*Dd];     // post double-LN
__device__ float g_xc [SEQ*Lseq*DI];     // conv+silu output
__device__ float g_z  [SEQ*Lseq*DI];     // gate branch
__device__ float g_bc [SEQ*Lseq*32];     // B(16)|C(16) per token
__device__ float g_dt [SEQ*Lseq*DI];     // softplus dt
__device__ float g_P  [SEQ*NC*DI*DS];    // chunk A-products
__device__ float g_Q  [SEQ*NC*DI*DS];    // chunk local scans
__device__ float g_hin[SEQ*NC*DI*DS];    // chunk initial states
__device__ float g_ym [SEQ*Lseq*DI];     // gated scan output
__device__ float g_zc [Bsz*Lseq*Cdim];   // concatenated split outputs
__device__ float g_pwt[Cdim*Cdim];       // transposed final proj weight

__device__ __forceinline__ float wsum(float v){
    #pragma unroll
    for(int o=16;o;o>>=1) v += __shfl_xor_sync(0xffffffffu, v, o);
    return v;
}
__device__ __forceinline__ float siluf(float x){ return x/(1.f+__expf(-x)); }

// ---------------- K0: transpose final projection weight ----------------
__global__ void k_tr(const float* __restrict__ pw){
    int i = blockIdx.x*256 + threadIdx.x;      // 16384
    int o = i>>7, c = i&127;
    g_pwt[c*128+o] = pw[i];
}

// ---------------- K1: LN over C, then per-split LN over D ----------------
__global__ void k_ln(const float* __restrict__ x, const float* __restrict__ lg,
                     const float* __restrict__ lb, const float* __restrict__ pg,
                     const float* __restrict__ pb){
    __shared__ float sx[128][33];
    int b = blockIdx.y, l0 = blockIdx.x*32, tid = threadIdx.x;
    for(int i=tid;i<128*32;i+=256){
        int c=i>>5, li=i&31;
        sx[c][li] = x[(b*128 + c)*Lseq + l0 + li];
    }
    __syncthreads();
    int w = tid>>5, lane = tid&31;
    for(int lc=w; lc<32; lc+=8){
        float v0=sx[lane][lc], v1=sx[lane+32][lc], v2=sx[lane+64][lc], v3=sx[lane+96][lc];
        float mu = wsum(v0+v1+v2+v3)*(1.f/128.f);
        float d0=v0-mu,d1=v1-mu,d2=v2-mu,d3=v3-mu;
        float rs = rsqrtf(wsum(d0*d0+d1*d1+d2*d2+d3*d3)*(1.f/128.f)+EPSf);
        float xn[4];
        xn[0]=d0*rs*lg[lane     ]+lb[lane     ];
        xn[1]=d1*rs*lg[lane+ 32]+lb[lane+ 32];
        xn[2]=d2*rs*lg[lane+ 64]+lb[lane+ 64];
        xn[3]=d3*rs*lg[lane+ 96]+lb[lane+ 96];
        #pragma unroll
        for(int g=0; g<4; g++){
            float mu2 = wsum(xn[g])*(1.f/32.f);
            float dd  = xn[g]-mu2;
            float rs2 = rsqrtf(wsum(dd*dd)*(1.f/32.f)+EPSf);
            float o = dd*rs2*pg[g*32+lane] + pb[g*32+lane];
            g_xn2[((g*Bsz + b)*Lseq + l0+lc)*Dd + lane] = o;
        }
    }
}

// ---- K2: fused in_proj + causal conv + SiLU + x_proj + dt (32-token tile, 3 halo) ----
__global__ void k_fused(const float* __restrict__ Win, const float* __restrict__ cw,
                        const float* __restrict__ cb,  const float* __restrict__ Wx,
                        const float* __restrict__ dtw, const float* __restrict__ dtb){
    __shared__ float sxz[35*128];      // xz for 35 tokens (halo 3)
    __shared__ float sxc[32*64];       // conv+silu result
    __shared__ float sbuf[2176];       // sxn (35*32), later sWx (64*34)
    __shared__ float sdtr[64];         // dt-rank projections (32 tokens x 2)
    int seq=blockIdx.y, g=seq>>2, tid=threadIdx.x;
    int l0 = blockIdx.x*TILE;

    float w[32];
    #pragma unroll
    for(int k=0;k<32;k++) w[k] = Win[g*4096 + k*128 + tid];

    for(int i=tid;i<35*32;i+=128){
        int j=i>>5, k=i&31, tt=l0-3+j;
        sbuf[i] = (tt>=0)? g_xn2[(seq*Lseq+tt)*32 + k] : 0.f;
    }
    __syncthreads();

    #pragma unroll 5
    for(int j=0;j<35;j++){
        float acc=0.f;
        #pragma unroll
        for(int k=0;k<32;k+=4){
            float4 v = *(const float4*)&sbuf[j*32+k];
            acc = fmaf(v.x,w[k  ],acc); acc = fmaf(v.y,w[k+1],acc);
            acc = fmaf(v.z,w[k+2],acc); acc = fmaf(v.w,w[k+3],acc);
        }
        sxz[j*128+tid]=acc;
    }
    __syncthreads();

    for(int i=tid;i<64*NPROJ;i+=128) sbuf[i] = Wx[g*64*NPROJ + i];

    {
        int ch = tid&63;
        float c0=cw[g*256+ch*4], c1=cw[g*256+ch*4+1], c2=cw[g*256+ch*4+2], c3=cw[g*256+ch*4+3];
        float bb=cb[g*64+ch];
        for(int t = tid>>6; t<32; t+=2){
            float acc = bb;
            acc = fmaf(sxz[ t   *128+ch], c0, acc);
            acc = fmaf(sxz[(t+1)*128+ch], c1, acc);
            acc = fmaf(sxz[(t+2)*128+ch], c2, acc);
            acc = fmaf(sxz[(t+3)*128+ch], c3, acc);
            float v = siluf(acc);
            sxc[t*64+ch] = v;
            g_xc[(seq*Lseq+l0+t)*64+ch] = v;
            g_z [(seq*Lseq+l0+t)*64+ch] = sxz[(t+3)*128 + 64 + ch];
        }
    }
    __syncthreads();

    for(int i=tid;i<32*NPROJ;i+=128){
        int t=i/NPROJ, n=i-t*NPROJ;
        float acc=0.f;
        #pragma unroll 8
        for(int k=0;k<64;k++) acc = fmaf(sxc[t*64+k], sbuf[k*NPROJ+n], acc);
        if(n<2) sdtr[t*2+n]=acc;
        else    g_bc[(seq*Lseq+l0+t)*32 + n-2]=acc;
    }
    __syncthreads();

    {
        int d = tid&63;
        float w0 = dtw[g*128+d], w1 = dtw[g*128+64+d], bb=dtb[g*64+d];
        for(int t=tid>>6;t<32;t+=2){
            float v = fmaf(sdtr[t*2],w0,fmaf(sdtr[t*2+1],w1,bb));
            g_dt[(seq*Lseq+l0+t)*64+d] = (v>20.f)? v : log1pf(__expf(v));
        }
    }
}

// ---------------- K3: scan phase 1 — per-chunk (P, Q) ----------------
// 256 threads = 4 chunks; no smem; coalesced dt/xc, uniform float4 B loads.
// P[s] = exp(A[s]*sum(dt)) computed once per chunk.
__global__ void k_scan1(const float* __restrict__ A_log){
    int seq=blockIdx.y, g=seq>>2;
    int sub=threadIdx.x>>6, d=threadIdx.x&63;
    int ck=blockIdx.x*4+sub;
    float A[DS], Q[DS];
    #pragma unroll
    for(int s=0;s<DS;s++){ A[s] = -__expf(A_log[(g*64+d)*16+s]); Q[s]=0.f; }
    int tb = ck*TC;
    const float* __restrict__ dtp = &g_dt[(seq*Lseq+tb)*64 + d];
    const float* __restrict__ xcp = &g_xc[(seq*Lseq+tb)*64 + d];
    const float* __restrict__ bcp = &g_bc[(seq*Lseq+tb)*32];
    float sdt = 0.f;
    #pragma unroll 4
    for(int t=0;t<TC;t++){
        float dtv = dtp[t*64];
        float dx  = dtv * xcp[t*64];
        sdt += dtv;
        float4 b0 = *(const float4*)&bcp[t*32];
        float4 b1 = *(const float4*)&bcp[t*32+4];
        float4 b2 = *(const float4*)&bcp[t*32+8];
        float4 b3 = *(const float4*)&bcp[t*32+12];
        float bb[16]={b0.x,b0.y,b0.z,b0.w,b1.x,b1.y,b1.z,b1.w,
                      b2.x,b2.y,b2.z,b2.w,b3.x,b3.y,b3.z,b3.w};
        #pragma unroll
        for(int s=0;s<DS;s++){
            float e = __expf(A[s]*dtv);
            Q[s] = fmaf(e, Q[s], dx*bb[s]);
        }
    }
    int base = ((seq*NC+ck)*64 + d)*16;
    #pragma unroll
    for(int s=0;s<16;s+=4){
        float4 p;
        p.x = __expf(A[s  ]*sdt);
        p.y = __expf(A[s+1]*sdt);
        p.z = __expf(A[s+2]*sdt);
        p.w = __expf(A[s+3]*sdt);
        *(float4*)&g_P[base+s] = p;
        *(float4*)&g_Q[base+s] = make_float4(Q[s],Q[s+1],Q[s+2],Q[s+3]);
    }
}

// ---------------- K4: scan phase 2 — sequential across chunks ----------------
__global__ void k_scan2(){
    int idx = blockIdx.x*128 + threadIdx.x;     // SEQ*1024 = 16384
    int lane = idx & 1023; int seq = idx >> 10;
    float h = 0.f;
    int base = seq*NC*1024 + lane;
    #pragma unroll 8
    for(int c=0;c<NC;c++){
        g_hin[base + c*1024] = h;
        h = fmaf(g_P[base + c*1024], h, g_Q[base + c*1024]);
    }
}

// ---------------- K5: scan phase 3 — replay + y + gate fusion ----------------
__global__ void k_scan3(const float* __restrict__ A_log, const float* __restrict__ Dpar){
    int seq=blockIdx.y, g=seq>>2;
    int sub=threadIdx.x>>6, d=threadIdx.x&63;
    int ck=blockIdx.x*4+sub;
    float A[DS], h[DS];
    #pragma unroll
    for(int s=0;s<DS;s++) A[s] = -__expf(A_log[(g*64+d)*16+s]);
    int hb = ((seq*NC+ck)*64 + d)*16;
    #pragma unroll
    for(int s=0;s<16;s+=4){
        float4 v = *(const float4*)&g_hin[hb+s];
        h[s]=v.x; h[s+1]=v.y; h[s+2]=v.z; h[s+3]=v.w;
    }
    float Dp = Dpar[g*64+d];
    int tb = ck*TC;
    const float* __restrict__ dtp = &g_dt[(seq*Lseq+tb)*64 + d];
    const float* __restrict__ xcp = &g_xc[(seq*Lseq+tb)*64 + d];
    const float* __restrict__ zp  = &g_z [(seq*Lseq+tb)*64 + d];
    const float* __restrict__ bcp = &g_bc[(seq*Lseq+tb)*32];
    float*       __restrict__ ymp = &g_ym[(seq*Lseq+tb)*64 + d];
    #pragma unroll 4
    for(int t=0;t<TC;t++){
        float dtv = dtp[t*64];
        float xcv = xcp[t*64];
        float dx  = dtv*xcv;
        float4 b0 = *(const float4*)&bcp[t*32];
        float4 b1 = *(const float4*)&bcp[t*32+4];
        float4 b2 = *(const float4*)&bcp[t*32+8];
        float4 b3 = *(const float4*)&bcp[t*32+12];
        float4 c0 = *(const float4*)&bcp[t*32+16];
        float4 c1 = *(const float4*)&bcp[t*32+20];
        float4 c2 = *(const float4*)&bcp[t*32+24];
        float4 c3 = *(const float4*)&bcp[t*32+28];
        float bb[16]={b0.x,b0.y,b0.z,b0.w,b1.x,b1.y,b1.z,b1.w,
                      b2.x,b2.y,b2.z,b2.w,b3.x,b3.y,b3.z,b3.w};
        float cc[16]={c0.x,c0.y,c0.z,c0.w,c1.x,c1.y,c1.z,c1.w,
                      c2.x,c2.y,c2.z,c2.w,c3.x,c3.y,c3.z,c3.w};
        float y = 0.f;
        #pragma unroll
        for(int s=0;s<DS;s++){
            float e = __expf(A[s]*dtv);
            h[s] = fmaf(e, h[s], dx*bb[s]);
            y = fmaf(h[s], cc[s], y);
        }
        ymp[t*64] = (y + Dp*xcv) * siluf(zp[t*64]);
    }
}

// ---------------- K6: out_proj(64->32) + skip + pvm_proj(32->32) ----------------
__global__ void k_out(const float* __restrict__ W1, const float* __restrict__ W2,
                      const float* __restrict__ pb2, const float* __restrict__ skipv){
    __shared__ float sW1[64*32], sW2[32*32], spb[32], su[8*32], sym[8*64];
    int seq=blockIdx.y, g=seq>>2, b=seq&3, t0=blockIdx.x*8, tid=threadIdx.x;
    for(int i=tid;i<2048;i+=256) sW1[i]=W1[g*2048+i];
    for(int i=tid;i<1024;i+=256) sW2[i]=W2[g*1024+i];
    if(tid<32) spb[tid]=pb2[g*32+tid];
    for(int i=tid;i<512;i+=256) sym[i]=g_ym[(seq*Lseq+t0)*64 + i];
    float skip = skipv[g];
    __syncthreads();
    int w = tid>>5, lane = tid&31;
    int t = t0 + w;
    float acc = 0.f;
    #pragma unroll 8
    for(int k=0;k<64;k++) acc = fmaf(sym[w*64+k], sW1[k*32+lane], acc);
    float u = acc + skip * g_xn2[(seq*Lseq+t)*32 + lane];
    su[w*32+lane] = u;
    __syncwarp();
    float acc2 = spb[lane];
    #pragma unroll 8
    for(int n=0;n<32;n++) acc2 = fmaf(su[w*32+n], sW2[n*32+lane], acc2);
    g_zc[(b*Lseq+t)*128 + g*32 + lane] = acc2;
}

// ---------------- K7: final proj (128x128) + BN + exact GELU ----------------
__global__ void k_final(const float* __restrict__ pb2, const float* __restrict__ bg,
                        const float* __restrict__ bb, const float* __restrict__ bm,
                        const float* __restrict__ bv, float* __restrict__ out){
    __shared__ float st[32*128];
    int b = blockIdx.y, l0 = blockIdx.x*32, o = threadIdx.x;
    for(int i=o;i<4096;i+=128) st[i] = g_zc[(b*Lseq+l0)*128 + i];
    float scale = bg[o]*rsqrtf(bv[o]+EPSf);
    float c0 = (pb2[o]-bm[o])*scale + bb[o];
    __syncthreads();
    float acc[32];
    #pragma unroll
    for(int t=0;t<32;t++) acc[t]=0.f;
    #pragma unroll 4
    for(int c=0;c<128;c++){
        float w = g_pwt[c*128+o];
        #pragma unroll
        for(int t=0;t<32;t++) acc[t] = fmaf(st[t*128+c], w, acc[t]);
    }
    __syncthreads();
    #pragma unroll
    for(int t=0;t<32;t++){
        float v = fmaf(acc[t], scale, c0);
        st[o*32+t] = 0.5f*v*(1.f + erff(v*0.70710678118654752f));
    }
    __syncthreads();
    for(int i=o;i<4096;i+=128){
        int oo = i>>5, li = i&31;
        out[(b*128+oo)*Lseq + l0 + li] = st[i];
    }
}

// ---------------- launch ----------------
extern "C" void kernel_launch(void* const* d_in, const int* in_sizes, int n_in,
                              void* d_out, int out_size){
    const float* x         = (const float*)d_in[0];
    const float* ln_g      = (const float*)d_in[1];
    const float* ln_b      = (const float*)d_in[2];
    const float* pvm_ln_g  = (const float*)d_in[3];
    const float* pvm_ln_b  = (const float*)d_in[4];
    const float* in_proj_w = (const float*)d_in[5];
    const float* conv_w    = (const float*)d_in[6];
    const float* conv_b    = (const float*)d_in[7];
    const float* x_proj_w  = (const float*)d_in[8];
    const float* dt_proj_w = (const float*)d_in[9];
    const float* dt_bias   = (const float*)d_in[10];
    const float* A_log     = (const float*)d_in[11];
    const float* D_param   = (const float*)d_in[12];
    const float* out_proj_w= (const float*)d_in[13];
    const float* skip_scale= (const float*)d_in[14];
    const float* pvm_proj_w= (const float*)d_in[15];
    const float* pvm_proj_b= (const float*)d_in[16];
    const float* proj_w    = (const float*)d_in[17];
    const float* proj_b    = (const float*)d_in[18];
    const float* bn_g      = (const float*)d_in[19];
    const float* bn_b      = (const float*)d_in[20];
    const float* bn_mean   = (const float*)d_in[21];
    const float* bn_var    = (const float*)d_in[22];
    float* out = (float*)d_out;

    k_tr    <<<64, 256>>>(proj_w);
    k_ln    <<<dim3(128,4), 256>>>(x, ln_g, ln_b, pvm_ln_g, pvm_ln_b);
    k_fused <<<dim3(Lseq/TILE,16), 128>>>(in_proj_w, conv_w, conv_b, x_proj_w, dt_proj_w, dt_bias);
    k_scan1 <<<dim3(NC/4,16), 256>>>(A_log);
    k_scan2 <<<128, 128>>>();
    k_scan3 <<<dim3(NC/4,16), 256>>>(A_log, D_param);
    k_out   <<<dim3(512,16), 256>>>(out_proj_w, pvm_proj_w, pvm_proj_b, skip_scale);
    k_final <<<dim3(128,4), 128>>>(proj_b, bn_g, bn_b, bn_mean, bn_var, out);
}

// round 9
// speedup vs baseline: 1.1708x; 1.1329x over previous
#include <cuda_runtime.h>
#include <math.h>

#define Bsz    4
#define Cdim   128
#define Lseq   4096
#define Dd     32
#define DI     64
#define DS     16
#define NPROJ  34
#define SEQ    16
#define NC     128
#define TC     32
#define EPSf   1e-5f

// ---------------- scratch (device globals) ----------------
__device__ float g_xn2 [SEQ*Lseq*Dd];       // post double-LN
__device__ float g_xz  [SEQ*Lseq*2*DI];     // in_proj output (xc_pre | z)
__device__ float g_xc  [SEQ*Lseq*DI];       // conv+silu output
__device__ float g_bc  [SEQ*Lseq*32];       // B(16)|C(16) per token
__device__ float g_dt  [SEQ*Lseq*DI];       // softplus dt
__device__ float g_P   [SEQ*NC*DI*DS];      // chunk A-products
__device__ float g_Q   [SEQ*NC*DI*DS];      // chunk local scans
__device__ float g_hin [SEQ*NC*DI*DS];      // chunk initial states
__device__ float g_ym  [SEQ*Lseq*DI];       // gated scan output
__device__ float g_zc  [Bsz*Lseq*Cdim];     // concatenated split outputs
__device__ float g_pwt [Cdim*Cdim];         // transposed final proj weight

__device__ __forceinline__ float wsum(float v){
    #pragma unroll
    for(int o=16;o;o>>=1) v += __shfl_xor_sync(0xffffffffu, v, o);
    return v;
}
__device__ __forceinline__ float siluf(float x){ return x/(1.f+__expf(-x)); }

// ---------------- K0: transpose final projection weight ----------------
__global__ void k_tr(const float* __restrict__ pw){
    int i = blockIdx.x*256 + threadIdx.x;      // 16384
    int o = i>>7, c = i&127;
    g_pwt[c*128+o] = pw[i];
}

// ---------------- K1: LN over C, then per-split LN over D ----------------
__global__ void k_ln(const float* __restrict__ x, const float* __restrict__ lg,
                     const float* __restrict__ lb, const float* __restrict__ pg,
                     const float* __restrict__ pb){
    __shared__ float sx[128][33];
    int b = blockIdx.y, l0 = blockIdx.x*32, tid = threadIdx.x;
    for(int i=tid;i<128*32;i+=256){
        int c=i>>5, li=i&31;
        sx[c][li] = x[(b*128 + c)*Lseq + l0 + li];
    }
    __syncthreads();
    int w = tid>>5, lane = tid&31;
    for(int lc=w; lc<32; lc+=8){
        float v0=sx[lane][lc], v1=sx[lane+32][lc], v2=sx[lane+64][lc], v3=sx[lane+96][lc];
        float mu = wsum(v0+v1+v2+v3)*(1.f/128.f);
        float d0=v0-mu,d1=v1-mu,d2=v2-mu,d3=v3-mu;
        float rs = rsqrtf(wsum(d0*d0+d1*d1+d2*d2+d3*d3)*(1.f/128.f)+EPSf);
        float xn[4];
        xn[0]=d0*rs*lg[lane     ]+lb[lane     ];
        xn[1]=d1*rs*lg[lane+ 32]+lb[lane+ 32];
        xn[2]=d2*rs*lg[lane+ 64]+lb[lane+ 64];
        xn[3]=d3*rs*lg[lane+ 96]+lb[lane+ 96];
        #pragma unroll
        for(int g=0; g<4; g++){
            float mu2 = wsum(xn[g])*(1.f/32.f);
            float dd  = xn[g]-mu2;
            float rs2 = rsqrtf(wsum(dd*dd)*(1.f/32.f)+EPSf);
            float o = dd*rs2*pg[g*32+lane] + pb[g*32+lane];
            g_xn2[((g*Bsz + b)*Lseq + l0+lc)*Dd + lane] = o;
        }
    }
}

// ---------------- K2: in_proj GEMM (32 -> 128) ----------------
__global__ void k_inproj(const float* __restrict__ W){
    __shared__ float sW[32*128];
    __shared__ float sx[32*32];
    int seq=blockIdx.y, l0=blockIdx.x*32, g=seq>>2, tid=threadIdx.x;
    for(int i=tid;i<4096;i+=128) sW[i] = W[g*4096+i];
    for(int i=tid;i<1024;i+=128) sx[i] = g_xn2[(seq*Lseq+l0)*32 + i];
    __syncthreads();
    float acc[32];
    #pragma unroll
    for(int t=0;t<32;t++) acc[t]=0.f;
    int n = tid;
    #pragma unroll 4
    for(int k=0;k<32;k++){
        float w = sW[k*128+n];
        #pragma unroll
        for(int t=0;t<32;t++) acc[t] = fmaf(sx[t*32+k], w, acc[t]);
    }
    #pragma unroll
    for(int t=0;t<32;t++) g_xz[(seq*Lseq+l0+t)*128 + n] = acc[t];
}

// ---------------- K3: causal conv(4) + bias + SiLU ----------------
__global__ void k_conv(const float* __restrict__ cw, const float* __restrict__ cb){
    int idx = blockIdx.x*256 + threadIdx.x;     // SEQ*L*DI = 2^22
    int ch = idx & 63; int t = (idx>>6) & (Lseq-1); int seq = idx >> 18;
    int g = seq>>2;
    float acc = cb[g*64+ch];
    const float* cwp = cw + g*256 + ch*4;
    #pragma unroll
    for(int k=0;k<4;k++){
        int tt = t-3+k;
        if(tt>=0) acc = fmaf(g_xz[(seq*Lseq+tt)*128 + ch], cwp[k], acc);
    }
    g_xc[idx] = siluf(acc);
}

// ---- K4: x_proj GEMM (64 -> 34) + fused dt softplus (128 thr, 64 tokens) ----
__global__ void k_xproj(const float* __restrict__ W, const float* __restrict__ dtw,
                        const float* __restrict__ dtb){
    __shared__ float sW[64*NPROJ];
    __shared__ float sx[64*64];
    __shared__ float sdtr[128];
    int seq=blockIdx.y, l0=blockIdx.x*64, g=seq>>2, tid=threadIdx.x;
    for(int i=tid;i<64*NPROJ;i+=128) sW[i] = W[g*64*NPROJ + i];
    for(int i=tid;i<4096;i+=128)     sx[i] = g_xc[(seq*Lseq+l0)*64 + i];
    __syncthreads();
    int sub = tid>>6, n = tid&63;           // sub selects 32-token half
    if(n < NPROJ){
        float acc[32];
        #pragma unroll
        for(int t=0;t<32;t++) acc[t]=0.f;
        #pragma unroll 4
        for(int k=0;k<64;k++){
            float w = sW[k*NPROJ + n];
            #pragma unroll
            for(int t=0;t<32;t++) acc[t] = fmaf(sx[(sub*32+t)*64+k], w, acc[t]);
        }
        #pragma unroll
        for(int t=0;t<32;t++){
            int tok = sub*32 + t;
            if(n<2) sdtr[tok*2+n]=acc[t];
            else    g_bc[(seq*Lseq+l0+tok)*32 + n-2]=acc[t];
        }
    }
    __syncthreads();
    {
        int d = tid&63;
        float w0 = dtw[g*128+d], w1 = dtw[g*128+64+d], bb=dtb[g*64+d];
        for(int t=tid>>6;t<64;t+=2){
            float v = fmaf(sdtr[t*2],w0,fmaf(sdtr[t*2+1],w1,bb));
            g_dt[(seq*Lseq+l0+t)*64+d] = (v>20.f)? v : log1pf(__expf(v));
        }
    }
}

// ---------------- K5: scan phase 1 — per-chunk (P, Q) ----------------
__global__ void k_scan1(const float* __restrict__ A_log){
    __shared__ float s_dt[16*64], s_xc[16*64], s_bc[16*16];
    int seq=blockIdx.y, ck=blockIdx.x, g=seq>>2, d=threadIdx.x;
    float A[DS], Q[DS];
    #pragma unroll
    for(int s=0;s<DS;s++){ A[s] = -__expf(A_log[(g*64+d)*16+s]); Q[s]=0.f; }
    int tbase = ck*TC;
    float sdt = 0.f;
    for(int sub=0; sub<TC/16; sub++){
        int tb = tbase + sub*16;
        __syncthreads();
        for(int i=d;i<1024;i+=64){
            s_dt[i]=g_dt[(seq*Lseq+tb)*64 + i];
            s_xc[i]=g_xc[(seq*Lseq+tb)*64 + i];
        }
        for(int i=d;i<256;i+=64){
            int t=i>>4, s=i&15;
            s_bc[i] = g_bc[(seq*Lseq+tb+t)*32 + s];
        }
        __syncthreads();
        #pragma unroll 4
        for(int i=0;i<16;i++){
            float dtv = s_dt[i*64+d];
            float dx  = dtv * s_xc[i*64+d];
            sdt += dtv;
            #pragma unroll
            for(int s=0;s<DS;s++){
                float e = __expf(A[s]*dtv);
                Q[s] = fmaf(e, Q[s], dx*s_bc[i*16+s]);
            }
        }
    }
    int base = ((seq*NC+ck)*64 + d)*16;
    #pragma unroll
    for(int s=0;s<16;s+=4){
        float4 p;
        p.x = __expf(A[s  ]*sdt);
        p.y = __expf(A[s+1]*sdt);
        p.z = __expf(A[s+2]*sdt);
        p.w = __expf(A[s+3]*sdt);
        *(float4*)&g_P[base+s] = p;
        *(float4*)&g_Q[base+s] = make_float4(Q[s],Q[s+1],Q[s+2],Q[s+3]);
    }
}

// ---------------- K6: scan phase 2 — sequential across chunks ----------------
__global__ void k_scan2(){
    int idx = blockIdx.x*128 + threadIdx.x;     // SEQ*1024 = 16384
    int lane = idx & 1023; int seq = idx >> 10;
    float h = 0.f;
    int base = seq*NC*1024 + lane;
    #pragma unroll 8
    for(int c=0;c<NC;c++){
        g_hin[base + c*1024] = h;
        h = fmaf(g_P[base + c*1024], h, g_Q[base + c*1024]);
    }
}

// ---------------- K7: scan phase 3 — replay + y + gate fusion ----------------
__global__ void k_scan3(const float* __restrict__ A_log, const float* __restrict__ Dpar){
    __shared__ float s_dt[1024], s_xc[1024], s_z[1024], s_bc[256], s_cc[256];
    int seq=blockIdx.y, ck=blockIdx.x, g=seq>>2, d=threadIdx.x;
    float A[DS], h[DS];
    #pragma unroll
    for(int s=0;s<DS;s++) A[s] = -__expf(A_log[(g*64+d)*16+s]);
    int hb = ((seq*NC+ck)*64 + d)*16;
    #pragma unroll
    for(int s=0;s<16;s+=4){
        float4 v = *(const float4*)&g_hin[hb+s];
        h[s]=v.x; h[s+1]=v.y; h[s+2]=v.z; h[s+3]=v.w;
    }
    float Dp = Dpar[g*64+d];
    int tbase = ck*TC;
    for(int sub=0; sub<TC/16; sub++){
        int tb = tbase + sub*16;
        __syncthreads();
        for(int i=d;i<1024;i+=64){
            s_dt[i]=g_dt[(seq*Lseq+tb)*64 + i];
            s_xc[i]=g_xc[(seq*Lseq+tb)*64 + i];
            int t=i>>6, dd=i&63;
            s_z[i] = g_xz[(seq*Lseq+tb+t)*128 + 64 + dd];
        }
        for(int i=d;i<256;i+=64){
            int t=i>>4, s=i&15;
            s_bc[i] = g_bc[(seq*Lseq+tb+t)*32 + s];
            s_cc[i] = g_bc[(seq*Lseq+tb+t)*32 + 16 + s];
        }
        __syncthreads();
        #pragma unroll 4
        for(int i=0;i<16;i++){
            float dtv = s_dt[i*64+d];
            float xcv = s_xc[i*64+d];
            float dx  = dtv*xcv;
            float y = 0.f;
            #pragma unroll
            for(int s=0;s<DS;s++){
                float e = __expf(A[s]*dtv);
                h[s] = fmaf(e, h[s], dx*s_bc[i*16+s]);
                y = fmaf(h[s], s_cc[i*16+s], y);
            }
            float zv = s_z[i*64+d];
            g_ym[(seq*Lseq+tb+i)*64 + d] = (y + Dp*xcv) * siluf(zv);
        }
    }
}

// ---------------- K8: out_proj(64->32) + skip + pvm_proj(32->32) ----------------
__global__ void k_out(const float* __restrict__ W1, const float* __restrict__ W2,
                      const float* __restrict__ pb2, const float* __restrict__ skipv){
    __shared__ float sW1[64*32], sW2[32*32], spb[32], su[8*32], sym[8*64];
    int seq=blockIdx.y, g=seq>>2, b=seq&3, t0=blockIdx.x*8, tid=threadIdx.x;
    for(int i=tid;i<2048;i+=256) sW1[i]=W1[g*2048+i];
    for(int i=tid;i<1024;i+=256) sW2[i]=W2[g*1024+i];
    if(tid<32) spb[tid]=pb2[g*32+tid];
    for(int i=tid;i<512;i+=256) sym[i]=g_ym[(seq*Lseq+t0)*64 + i];
    float skip = skipv[g];
    __syncthreads();
    int w = tid>>5, lane = tid&31;
    int t = t0 + w;
    float acc = 0.f;
    #pragma unroll 8
    for(int k=0;k<64;k++) acc = fmaf(sym[w*64+k], sW1[k*32+lane], acc);
    float u = acc + skip * g_xn2[(seq*Lseq+t)*32 + lane];
    su[w*32+lane] = u;
    __syncwarp();
    float acc2 = spb[lane];
    #pragma unroll 8
    for(int n=0;n<32;n++) acc2 = fmaf(su[w*32+n], sW2[n*32+lane], acc2);
    g_zc[(b*Lseq+t)*128 + g*32 + lane] = acc2;
}

// ---------------- K9: final proj (128x128) + BN + exact GELU ----------------
__global__ void k_final(const float* __restrict__ pb2, const float* __restrict__ bg,
                        const float* __restrict__ bb, const float* __restrict__ bm,
                        const float* __restrict__ bv, float* __restrict__ out){
    __shared__ float st[32*128];
    int b = blockIdx.y, l0 = blockIdx.x*32, o = threadIdx.x;
    for(int i=o;i<4096;i+=128) st[i] = g_zc[(b*Lseq+l0)*128 + i];
    float scale = bg[o]*rsqrtf(bv[o]+EPSf);
    float c0 = (pb2[o]-bm[o])*scale + bb[o];
    __syncthreads();
    float acc[32];
    #pragma unroll
    for(int t=0;t<32;t++) acc[t]=0.f;
    #pragma unroll 4
    for(int c=0;c<128;c++){
        float w = g_pwt[c*128+o];
        #pragma unroll
        for(int t=0;t<32;t++) acc[t] = fmaf(st[t*128+c], w, acc[t]);
    }
    __syncthreads();
    #pragma unroll
    for(int t=0;t<32;t++){
        float v = fmaf(acc[t], scale, c0);
        st[o*32+t] = 0.5f*v*(1.f + erff(v*0.70710678118654752f));
    }
    __syncthreads();
    for(int i=o;i<4096;i+=128){
        int oo = i>>5, li = i&31;
        out[(b*128+oo)*Lseq + l0 + li] = st[i];
    }
}

// ---------------- launch ----------------
extern "C" void kernel_launch(void* const* d_in, const int* in_sizes, int n_in,
                              void* d_out, int out_size){
    const float* x         = (const float*)d_in[0];
    const float* ln_g      = (const float*)d_in[1];
    const float* ln_b      = (const float*)d_in[2];
    const float* pvm_ln_g  = (const float*)d_in[3];
    const float* pvm_ln_b  = (const float*)d_in[4];
    const float* in_proj_w = (const float*)d_in[5];
    const float* conv_w    = (const float*)d_in[6];
    const float* conv_b    = (const float*)d_in[7];
    const float* x_proj_w  = (const float*)d_in[8];
    const float* dt_proj_w = (const float*)d_in[9];
    const float* dt_bias   = (const float*)d_in[10];
    const float* A_log     = (const float*)d_in[11];
    const float* D_param   = (const float*)d_in[12];
    const float* out_proj_w= (const float*)d_in[13];
    const float* skip_scale= (const float*)d_in[14];
    const float* pvm_proj_w= (const float*)d_in[15];
    const float* pvm_proj_b= (const float*)d_in[16];
    const float* proj_w    = (const float*)d_in[17];
    const float* proj_b    = (const float*)d_in[18];
    const float* bn_g      = (const float*)d_in[19];
    const float* bn_b      = (const float*)d_in[20];
    const float* bn_mean   = (const float*)d_in[21];
    const float* bn_var    = (const float*)d_in[22];
    float* out = (float*)d_out;

    k_tr    <<<64, 256>>>(proj_w);
    k_ln    <<<dim3(128,4), 256>>>(x, ln_g, ln_b, pvm_ln_g, pvm_ln_b);
    k_inproj<<<dim3(128,16), 128>>>(in_proj_w);
    k_conv  <<<16384, 256>>>(conv_w, conv_b);
    k_xproj <<<dim3(64,16), 128>>>(x_proj_w, dt_proj_w, dt_bias);
    k_scan1 <<<dim3(NC,16), 64>>>(A_log);
    k_scan2 <<<128, 128>>>();
    k_scan3 <<<dim3(NC,16), 64>>>(A_log, D_param);
    k_out   <<<dim3(512,16), 256>>>(out_proj_w, pvm_proj_w, pvm_proj_b, skip_scale);
    k_final <<<dim3(128,4), 128>>>(proj_b, bn_g, bn_b, bn_mean, bn_var, out);
}

// round 10
// speedup vs baseline: 1.2340x; 1.0540x over previous
#include <cuda_runtime.h>
#include <math.h>

#define Bsz    4
#define Cdim   128
#define Lseq   4096
#define Dd     32
#define DI     64
#define DS     16
#define NPROJ  34
#define SEQ    16
#define NC     128
#define TC     32
#define EPSf   1e-5f

// ---------------- scratch (device globals) ----------------
__device__ float g_xn2 [SEQ*Lseq*Dd];       // post double-LN
__device__ float g_xc  [SEQ*Lseq*DI];       // conv+silu output
__device__ float g_z   [SEQ*Lseq*DI];       // gate branch
__device__ float g_bc  [SEQ*Lseq*32];       // B(16)|C(16) per token
__device__ float g_dt  [SEQ*Lseq*DI];       // softplus dt
__device__ float g_P   [SEQ*NC*DI*DS];      // chunk A-products
__device__ float g_Q   [SEQ*NC*DI*DS];      // chunk local scans
__device__ float g_hin [SEQ*NC*DI*DS];      // chunk initial states
__device__ float g_ym  [SEQ*Lseq*DI];       // gated scan output
__device__ float g_zc  [Bsz*Lseq*Cdim];     // concatenated split outputs
__device__ float g_pwt [Cdim*Cdim];         // transposed final proj weight

__device__ __forceinline__ float wsum(float v){
    #pragma unroll
    for(int o=16;o;o>>=1) v += __shfl_xor_sync(0xffffffffu, v, o);
    return v;
}
__device__ __forceinline__ float siluf(float x){ return x/(1.f+__expf(-x)); }

// ---------------- K0: transpose final projection weight ----------------
__global__ void k_tr(const float* __restrict__ pw){
    int i = blockIdx.x*256 + threadIdx.x;      // 16384
    int o = i>>7, c = i&127;
    g_pwt[c*128+o] = pw[i];
}

// ---------------- K1: LN over C, then per-split LN over D ----------------
__global__ void k_ln(const float* __restrict__ x, const float* __restrict__ lg,
                     const float* __restrict__ lb, const float* __restrict__ pg,
                     const float* __restrict__ pb){
    __shared__ float sx[128][33];
    int b = blockIdx.y, l0 = blockIdx.x*32, tid = threadIdx.x;
    for(int i=tid;i<128*32;i+=256){
        int c=i>>5, li=i&31;
        sx[c][li] = x[(b*128 + c)*Lseq + l0 + li];
    }
    __syncthreads();
    int w = tid>>5, lane = tid&31;
    for(int lc=w; lc<32; lc+=8){
        float v0=sx[lane][lc], v1=sx[lane+32][lc], v2=sx[lane+64][lc], v3=sx[lane+96][lc];
        float mu = wsum(v0+v1+v2+v3)*(1.f/128.f);
        float d0=v0-mu,d1=v1-mu,d2=v2-mu,d3=v3-mu;
        float rs = rsqrtf(wsum(d0*d0+d1*d1+d2*d2+d3*d3)*(1.f/128.f)+EPSf);
        float xn[4];
        xn[0]=d0*rs*lg[lane     ]+lb[lane     ];
        xn[1]=d1*rs*lg[lane+ 32]+lb[lane+ 32];
        xn[2]=d2*rs*lg[lane+ 64]+lb[lane+ 64];
        xn[3]=d3*rs*lg[lane+ 96]+lb[lane+ 96];
        #pragma unroll
        for(int g=0; g<4; g++){
            float mu2 = wsum(xn[g])*(1.f/32.f);
            float dd  = xn[g]-mu2;
            float rs2 = rsqrtf(wsum(dd*dd)*(1.f/32.f)+EPSf);
            float o = dd*rs2*pg[g*32+lane] + pb[g*32+lane];
            g_xn2[((g*Bsz + b)*Lseq + l0+lc)*Dd + lane] = o;
        }
    }
}

// ---- K2: fused in_proj (32->128) + causal conv(4) + SiLU ----
// Thread tid owns output channel; acc[] holds its 35-token time series, so the
// conv is register-local (no smem exchange, no g_xz round trip).
__global__ void k_inconv(const float* __restrict__ W, const float* __restrict__ cw,
                         const float* __restrict__ cb){
    __shared__ float sx[35*32];
    int seq=blockIdx.y, l0=blockIdx.x*32, g=seq>>2, tid=threadIdx.x;
    float w[32];
    #pragma unroll
    for(int k=0;k<32;k++) w[k] = W[g*4096 + k*128 + tid];
    for(int i=tid;i<35*32;i+=128){
        int j=i>>5, k=i&31, tt=l0-3+j;
        sx[i] = (tt>=0)? g_xn2[(seq*Lseq+tt)*32 + k] : 0.f;
    }
    __syncthreads();
    float acc[35];
    #pragma unroll
    for(int j=0;j<35;j++) acc[j]=0.f;
    #pragma unroll 8
    for(int k=0;k<32;k++){
        float wk = w[k];
        #pragma unroll
        for(int j=0;j<35;j++) acc[j] = fmaf(sx[j*32+k], wk, acc[j]);
    }
    if(tid < 64){
        int ch = tid;
        const float* cwp = cw + g*256 + ch*4;
        float c0=cwp[0], c1=cwp[1], c2=cwp[2], c3=cwp[3], bb=cb[g*64+ch];
        #pragma unroll
        for(int t=0;t<32;t++){
            float v = bb;
            v = fmaf(acc[t  ], c0, v);
            v = fmaf(acc[t+1], c1, v);
            v = fmaf(acc[t+2], c2, v);
            v = fmaf(acc[t+3], c3, v);
            g_xc[(seq*Lseq+l0+t)*64+ch] = siluf(v);
        }
    } else {
        int ch = tid-64;
        #pragma unroll
        for(int t=0;t<32;t++)
            g_z[(seq*Lseq+l0+t)*64+ch] = acc[t+3];
    }
}

// ---- K3: x_proj GEMM (64 -> 34) + fused dt softplus (128 thr, 64 tokens) ----
__global__ void k_xproj(const float* __restrict__ W, const float* __restrict__ dtw,
                        const float* __restrict__ dtb){
    __shared__ float sW[64*NPROJ];
    __shared__ float sx[64*64];
    __shared__ float sdtr[128];
    int seq=blockIdx.y, l0=blockIdx.x*64, g=seq>>2, tid=threadIdx.x;
    for(int i=tid;i<64*NPROJ;i+=128) sW[i] = W[g*64*NPROJ + i];
    for(int i=tid;i<4096;i+=128)     sx[i] = g_xc[(seq*Lseq+l0)*64 + i];
    __syncthreads();
    int sub = tid>>6, n = tid&63;
    if(n < NPROJ){
        float acc[32];
        #pragma unroll
        for(int t=0;t<32;t++) acc[t]=0.f;
        #pragma unroll 4
        for(int k=0;k<64;k++){
            float w = sW[k*NPROJ + n];
            #pragma unroll
            for(int t=0;t<32;t++) acc[t] = fmaf(sx[(sub*32+t)*64+k], w, acc[t]);
        }
        #pragma unroll
        for(int t=0;t<32;t++){
            int tok = sub*32 + t;
            if(n<2) sdtr[tok*2+n]=acc[t];
            else    g_bc[(seq*Lseq+l0+tok)*32 + n-2]=acc[t];
        }
    }
    __syncthreads();
    {
        int d = tid&63;
        float w0 = dtw[g*128+d], w1 = dtw[g*128+64+d], bb=dtb[g*64+d];
        for(int t=tid>>6;t<64;t+=2){
            float v = fmaf(sdtr[t*2],w0,fmaf(sdtr[t*2+1],w1,bb));
            g_dt[(seq*Lseq+l0+t)*64+d] = (v>20.f)? v : log1pf(__expf(v));
        }
    }
}

// ---------------- K4: scan phase 1 — per-chunk (P, Q) ----------------
__global__ void k_scan1(const float* __restrict__ A_log){
    __shared__ float s_dt[16*64], s_xc[16*64], s_bc[16*16];
    int seq=blockIdx.y, ck=blockIdx.x, g=seq>>2, d=threadIdx.x;
    float A[DS], Q[DS];
    #pragma unroll
    for(int s=0;s<DS;s++){ A[s] = -__expf(A_log[(g*64+d)*16+s]); Q[s]=0.f; }
    int tbase = ck*TC;
    float sdt = 0.f;
    for(int sub=0; sub<TC/16; sub++){
        int tb = tbase + sub*16;
        __syncthreads();
        for(int i=d;i<1024;i+=64){
            s_dt[i]=g_dt[(seq*Lseq+tb)*64 + i];
            s_xc[i]=g_xc[(seq*Lseq+tb)*64 + i];
        }
        for(int i=d;i<256;i+=64){
            int t=i>>4, s=i&15;
            s_bc[i] = g_bc[(seq*Lseq+tb+t)*32 + s];
        }
        __syncthreads();
        #pragma unroll 4
        for(int i=0;i<16;i++){
            float dtv = s_dt[i*64+d];
            float dx  = dtv * s_xc[i*64+d];
            sdt += dtv;
            #pragma unroll
            for(int s=0;s<DS;s++){
                float e = __expf(A[s]*dtv);
                Q[s] = fmaf(e, Q[s], dx*s_bc[i*16+s]);
            }
        }
    }
    int base = ((seq*NC+ck)*64 + d)*16;
    #pragma unroll
    for(int s=0;s<16;s+=4){
        float4 p;
        p.x = __expf(A[s  ]*sdt);
        p.y = __expf(A[s+1]*sdt);
        p.z = __expf(A[s+2]*sdt);
        p.w = __expf(A[s+3]*sdt);
        *(float4*)&g_P[base+s] = p;
        *(float4*)&g_Q[base+s] = make_float4(Q[s],Q[s+1],Q[s+2],Q[s+3]);
    }
}

// ---------------- K5: scan phase 2 — sequential across chunks ----------------
__global__ void k_scan2(){
    int idx = blockIdx.x*128 + threadIdx.x;     // SEQ*1024 = 16384
    int lane = idx & 1023; int seq = idx >> 10;
    float h = 0.f;
    int base = seq*NC*1024 + lane;
    #pragma unroll 8
    for(int c=0;c<NC;c++){
        g_hin[base + c*1024] = h;
        h = fmaf(g_P[base + c*1024], h, g_Q[base + c*1024]);
    }
}

// ---------------- K6: scan phase 3 — replay + y + gate fusion ----------------
__global__ void k_scan3(const float* __restrict__ A_log, const float* __restrict__ Dpar){
    __shared__ float s_dt[1024], s_xc[1024], s_z[1024], s_bc[256], s_cc[256];
    int seq=blockIdx.y, ck=blockIdx.x, g=seq>>2, d=threadIdx.x;
    float A[DS], h[DS];
    #pragma unroll
    for(int s=0;s<DS;s++) A[s] = -__expf(A_log[(g*64+d)*16+s]);
    int hb = ((seq*NC+ck)*64 + d)*16;
    #pragma unroll
    for(int s=0;s<16;s+=4){
        float4 v = *(const float4*)&g_hin[hb+s];
        h[s]=v.x; h[s+1]=v.y; h[s+2]=v.z; h[s+3]=v.w;
    }
    float Dp = Dpar[g*64+d];
    int tbase = ck*TC;
    for(int sub=0; sub<TC/16; sub++){
        int tb = tbase + sub*16;
        __syncthreads();
        for(int i=d;i<1024;i+=64){
            s_dt[i]=g_dt[(seq*Lseq+tb)*64 + i];
            s_xc[i]=g_xc[(seq*Lseq+tb)*64 + i];
            s_z [i]=g_z [(seq*Lseq+tb)*64 + i];
        }
        for(int i=d;i<256;i+=64){
            int t=i>>4, s=i&15;
            s_bc[i] = g_bc[(seq*Lseq+tb+t)*32 + s];
            s_cc[i] = g_bc[(seq*Lseq+tb+t)*32 + 16 + s];
        }
        __syncthreads();
        #pragma unroll 4
        for(int i=0;i<16;i++){
            float dtv = s_dt[i*64+d];
            float xcv = s_xc[i*64+d];
            float dx  = dtv*xcv;
            float y = 0.f;
            #pragma unroll
            for(int s=0;s<DS;s++){
                float e = __expf(A[s]*dtv);
                h[s] = fmaf(e, h[s], dx*s_bc[i*16+s]);
                y = fmaf(h[s], s_cc[i*16+s], y);
            }
            float zv = s_z[i*64+d];
            g_ym[(seq*Lseq+tb+i)*64 + d] = (y + Dp*xcv) * siluf(zv);
        }
    }
}

// ---------------- K7: out_proj(64->32) + skip + pvm_proj(32->32), 32 tok/block ----
__global__ void k_out(const float* __restrict__ W1, const float* __restrict__ W2,
                      const float* __restrict__ pb2, const float* __restrict__ skipv){
    __shared__ float sW1[64*32], sW2[32*32], spb[32], su[8*32], sym[32*64];
    int seq=blockIdx.y, g=seq>>2, b=seq&3, t0=blockIdx.x*32, tid=threadIdx.x;
    for(int i=tid;i<2048;i+=256) sW1[i]=W1[g*2048+i];
    for(int i=tid;i<1024;i+=256) sW2[i]=W2[g*1024+i];
    if(tid<32) spb[tid]=pb2[g*32+tid];
    for(int i=tid;i<2048;i+=256) sym[i]=g_ym[(seq*Lseq+t0)*64 + i];
    float skip = skipv[g];
    __syncthreads();
    int w = tid>>5, lane = tid&31;
    #pragma unroll
    for(int it=0; it<4; it++){
        int tl = it*8 + w;
        int t  = t0 + tl;
        float acc = 0.f;
        #pragma unroll 8
        for(int k=0;k<64;k++) acc = fmaf(sym[tl*64+k], sW1[k*32+lane], acc);
        float u = acc + skip * g_xn2[(seq*Lseq+t)*32 + lane];
        su[w*32+lane] = u;
        __syncwarp();
        float acc2 = spb[lane];
        #pragma unroll 8
        for(int n=0;n<32;n++) acc2 = fmaf(su[w*32+n], sW2[n*32+lane], acc2);
        g_zc[(b*Lseq+t)*128 + g*32 + lane] = acc2;
        __syncwarp();
    }
}

// ---------------- K8: final proj (128x128) + BN + exact GELU ----------------
__global__ void k_final(const float* __restrict__ pb2, const float* __restrict__ bg,
                        const float* __restrict__ bb, const float* __restrict__ bm,
                        const float* __restrict__ bv, float* __restrict__ out){
    __shared__ float st[32*128];
    int b = blockIdx.y, l0 = blockIdx.x*32, o = threadIdx.x;
    for(int i=o;i<4096;i+=128) st[i] = g_zc[(b*Lseq+l0)*128 + i];
    float scale = bg[o]*rsqrtf(bv[o]+EPSf);
    float c0 = (pb2[o]-bm[o])*scale + bb[o];
    __syncthreads();
    float acc[32];
    #pragma unroll
    for(int t=0;t<32;t++) acc[t]=0.f;
    #pragma unroll 4
    for(int c=0;c<128;c++){
        float w = g_pwt[c*128+o];
        #pragma unroll
        for(int t=0;t<32;t++) acc[t] = fmaf(st[t*128+c], w, acc[t]);
    }
    __syncthreads();
    #pragma unroll
    for(int t=0;t<32;t++){
        float v = fmaf(acc[t], scale, c0);
        st[o*32+t] = 0.5f*v*(1.f + erff(v*0.70710678118654752f));
    }
    __syncthreads();
    for(int i=o;i<4096;i+=128){
        int oo = i>>5, li = i&31;
        out[(b*128+oo)*Lseq + l0 + li] = st[i];
    }
}

// ---------------- launch ----------------
extern "C" void kernel_launch(void* const* d_in, const int* in_sizes, int n_in,
                              void* d_out, int out_size){
    const float* x         = (const float*)d_in[0];
    const float* ln_g      = (const float*)d_in[1];
    const float* ln_b      = (const float*)d_in[2];
    const float* pvm_ln_g  = (const float*)d_in[3];
    const float* pvm_ln_b  = (const float*)d_in[4];
    const float* in_proj_w = (const float*)d_in[5];
    const float* conv_w    = (const float*)d_in[6];
    const float* conv_b    = (const float*)d_in[7];
    const float* x_proj_w  = (const float*)d_in[8];
    const float* dt_proj_w = (const float*)d_in[9];
    const float* dt_bias   = (const float*)d_in[10];
    const float* A_log     = (const float*)d_in[11];
    const float* D_param   = (const float*)d_in[12];
    const float* out_proj_w= (const float*)d_in[13];
    const float* skip_scale= (const float*)d_in[14];
    const float* pvm_proj_w= (const float*)d_in[15];
    const float* pvm_proj_b= (const float*)d_in[16];
    const float* proj_w    = (const float*)d_in[17];
    const float* proj_b    = (const float*)d_in[18];
    const float* bn_g      = (const float*)d_in[19];
    const float* bn_b      = (const float*)d_in[20];
    const float* bn_mean   = (const float*)d_in[21];
    const float* bn_var    = (const float*)d_in[22];
    float* out = (float*)d_out;

    k_tr    <<<64, 256>>>(proj_w);
    k_ln    <<<dim3(128,4), 256>>>(x, ln_g, ln_b, pvm_ln_g, pvm_ln_b);
    k_inconv<<<dim3(128,16), 128>>>(in_proj_w, conv_w, conv_b);
    k_xproj <<<dim3(64,16), 128>>>(x_proj_w, dt_proj_w, dt_bias);
    k_scan1 <<<dim3(NC,16), 64>>>(A_log);
    k_scan2 <<<128, 128>>>();
    k_scan3 <<<dim3(NC,16), 64>>>(A_log, D_param);
    k_out   <<<dim3(128,16), 256>>>(out_proj_w, pvm_proj_w, pvm_proj_b, skip_scale);
    k_final <<<dim3(128,4), 128>>>(proj_b, bn_g, bn_b, bn_mean, bn_var, out);
}

// round 11
// speedup vs baseline: 1.3221x; 1.0714x over previous
#include <cuda_runtime.h>
#include <math.h>

#define Bsz    4
#define Cdim   128
#define Lseq   4096
#define Dd     32
#define DI     64
#define DS     16
#define NPROJ  34
#define SEQ    16
#define NC     128
#define TC     32
#define EPSf   1e-5f

// ---------------- scratch (device globals) ----------------
__device__ float g_xn2 [SEQ*Lseq*Dd];       // post double-LN
__device__ float g_xc  [SEQ*Lseq*DI];       // conv+silu output
__device__ float g_z   [SEQ*Lseq*DI];       // gate branch
__device__ float g_bc  [SEQ*Lseq*32];       // B(16)|C(16) per token
__device__ float g_dt  [SEQ*Lseq*DI];       // softplus dt
__device__ float g_P   [SEQ*NC*DI*DS];      // chunk A-products
__device__ float g_Q   [SEQ*NC*DI*DS];      // chunk local scans
__device__ float g_hin [SEQ*NC*DI*DS];      // chunk initial states
__device__ float g_ym  [SEQ*Lseq*DI];       // gated scan output
__device__ float g_zc  [Bsz*Lseq*Cdim];     // concatenated split outputs
__device__ float g_pwt [Cdim*Cdim];         // transposed final proj weight

__device__ __forceinline__ float wsum(float v){
    #pragma unroll
    for(int o=16;o;o>>=1) v += __shfl_xor_sync(0xffffffffu, v, o);
    return v;
}
__device__ __forceinline__ float siluf(float x){ return x/(1.f+__expf(-x)); }

// ---------------- K0: transpose final projection weight ----------------
__global__ void k_tr(const float* __restrict__ pw){
    int i = blockIdx.x*256 + threadIdx.x;      // 16384
    int o = i>>7, c = i&127;
    g_pwt[c*128+o] = pw[i];
}

// ---------------- K1: LN over C, then per-split LN over D ----------------
__global__ void k_ln(const float* __restrict__ x, const float* __restrict__ lg,
                     const float* __restrict__ lb, const float* __restrict__ pg,
                     const float* __restrict__ pb){
    __shared__ float sx[128][33];
    int b = blockIdx.y, l0 = blockIdx.x*32, tid = threadIdx.x;
    for(int i=tid;i<128*32;i+=256){
        int c=i>>5, li=i&31;
        sx[c][li] = x[(b*128 + c)*Lseq + l0 + li];
    }
    __syncthreads();
    int w = tid>>5, lane = tid&31;
    for(int lc=w; lc<32; lc+=8){
        float v0=sx[lane][lc], v1=sx[lane+32][lc], v2=sx[lane+64][lc], v3=sx[lane+96][lc];
        float mu = wsum(v0+v1+v2+v3)*(1.f/128.f);
        float d0=v0-mu,d1=v1-mu,d2=v2-mu,d3=v3-mu;
        float rs = rsqrtf(wsum(d0*d0+d1*d1+d2*d2+d3*d3)*(1.f/128.f)+EPSf);
        float xn[4];
        xn[0]=d0*rs*lg[lane     ]+lb[lane     ];
        xn[1]=d1*rs*lg[lane+ 32]+lb[lane+ 32];
        xn[2]=d2*rs*lg[lane+ 64]+lb[lane+ 64];
        xn[3]=d3*rs*lg[lane+ 96]+lb[lane+ 96];
        #pragma unroll
        for(int g=0; g<4; g++){
            float mu2 = wsum(xn[g])*(1.f/32.f);
            float dd  = xn[g]-mu2;
            float rs2 = rsqrtf(wsum(dd*dd)*(1.f/32.f)+EPSf);
            float o = dd*rs2*pg[g*32+lane] + pb[g*32+lane];
            g_xn2[((g*Bsz + b)*Lseq + l0+lc)*Dd + lane] = o;
        }
    }
}

// ---- K2: fused in_proj (32->128) + causal conv(4) + SiLU ----
__global__ void k_inconv(const float* __restrict__ W, const float* __restrict__ cw,
                         const float* __restrict__ cb){
    __shared__ float sx[35*32];
    int seq=blockIdx.y, l0=blockIdx.x*32, g=seq>>2, tid=threadIdx.x;
    float w[32];
    #pragma unroll
    for(int k=0;k<32;k++) w[k] = W[g*4096 + k*128 + tid];
    for(int i=tid;i<35*32;i+=128){
        int j=i>>5, k=i&31, tt=l0-3+j;
        sx[i] = (tt>=0)? g_xn2[(seq*Lseq+tt)*32 + k] : 0.f;
    }
    __syncthreads();
    float acc[35];
    #pragma unroll
    for(int j=0;j<35;j++) acc[j]=0.f;
    #pragma unroll 8
    for(int k=0;k<32;k++){
        float wk = w[k];
        #pragma unroll
        for(int j=0;j<35;j++) acc[j] = fmaf(sx[j*32+k], wk, acc[j]);
    }
    if(tid < 64){
        int ch = tid;
        const float* cwp = cw + g*256 + ch*4;
        float c0=cwp[0], c1=cwp[1], c2=cwp[2], c3=cwp[3], bb=cb[g*64+ch];
        #pragma unroll
        for(int t=0;t<32;t++){
            float v = bb;
            v = fmaf(acc[t  ], c0, v);
            v = fmaf(acc[t+1], c1, v);
            v = fmaf(acc[t+2], c2, v);
            v = fmaf(acc[t+3], c3, v);
            g_xc[(seq*Lseq+l0+t)*64+ch] = siluf(v);
        }
    } else {
        int ch = tid-64;
        #pragma unroll
        for(int t=0;t<32;t++)
            g_z[(seq*Lseq+l0+t)*64+ch] = acc[t+3];
    }
}

// ---- K3: x_proj GEMM (64->34), token-per-thread + fused dt softplus ----
// 128 threads = 128 tokens; acc[34] in regs; xc row via padded float4 LDS;
// sW via warp-broadcast LDS; B/C restaged through padded smem for coalesced stores.
__global__ void k_xproj(const float* __restrict__ W, const float* __restrict__ dtw,
                        const float* __restrict__ dtb){
    __shared__ float sW[64*NPROJ];     // 2176
    __shared__ float sx[128*68];       // padded rows; later reused as bc staging
    __shared__ float sdtr[256];
    int seq=blockIdx.y, l0=blockIdx.x*128, g=seq>>2, tid=threadIdx.x;
    for(int i=tid;i<64*NPROJ;i+=128) sW[i] = W[g*64*NPROJ + i];
    for(int i=tid;i<128*64;i+=128){
        int t=i>>6, k=i&63;
        sx[t*68+k] = g_xc[(seq*Lseq+l0)*64 + i];
    }
    __syncthreads();
    float acc[NPROJ];
    #pragma unroll
    for(int n=0;n<NPROJ;n++) acc[n]=0.f;
    int t = tid;
    #pragma unroll 2
    for(int k=0;k<64;k+=4){
        float4 xv = *(const float4*)&sx[t*68+k];
        #pragma unroll
        for(int n=0;n<NPROJ;n++){
            float a = acc[n];
            a = fmaf(xv.x, sW[(k  )*NPROJ+n], a);
            a = fmaf(xv.y, sW[(k+1)*NPROJ+n], a);
            a = fmaf(xv.z, sW[(k+2)*NPROJ+n], a);
            a = fmaf(xv.w, sW[(k+3)*NPROJ+n], a);
            acc[n] = a;
        }
    }
    sdtr[t*2]   = acc[0];
    sdtr[t*2+1] = acc[1];
    __syncthreads();                       // all sx reads done
    #pragma unroll
    for(int n=0;n<32;n++) sx[t*33+n] = acc[n+2];   // conflict-free staging
    __syncthreads();
    for(int i=tid;i<128*32;i+=128){
        int tt=i>>5, n=i&31;
        g_bc[(seq*Lseq+l0)*32 + i] = sx[tt*33+n];
    }
    {
        int d = tid&63;
        float w0 = dtw[g*128+d], w1 = dtw[g*128+64+d], bb=dtb[g*64+d];
        for(int tt=tid>>6; tt<128; tt+=2){
            float v = fmaf(sdtr[tt*2],w0,fmaf(sdtr[tt*2+1],w1,bb));
            g_dt[(seq*Lseq+l0+tt)*64+d] = (v>20.f)? v : log1pf(__expf(v));
        }
    }
}

// ---------------- K4: scan phase 1 — per-chunk (P, Q) ----------------
__global__ void k_scan1(const float* __restrict__ A_log){
    __shared__ float s_dt[16*64], s_xc[16*64], s_bc[16*16];
    int seq=blockIdx.y, ck=blockIdx.x, g=seq>>2, d=threadIdx.x;
    float A[DS], Q[DS];
    #pragma unroll
    for(int s=0;s<DS;s++){ A[s] = -__expf(A_log[(g*64+d)*16+s]); Q[s]=0.f; }
    int tbase = ck*TC;
    float sdt = 0.f;
    for(int sub=0; sub<TC/16; sub++){
        int tb = tbase + sub*16;
        __syncthreads();
        for(int i=d;i<1024;i+=64){
            s_dt[i]=g_dt[(seq*Lseq+tb)*64 + i];
            s_xc[i]=g_xc[(seq*Lseq+tb)*64 + i];
        }
        for(int i=d;i<256;i+=64){
            int t=i>>4, s=i&15;
            s_bc[i] = g_bc[(seq*Lseq+tb+t)*32 + s];
        }
        __syncthreads();
        #pragma unroll 4
        for(int i=0;i<16;i++){
            float dtv = s_dt[i*64+d];
            float dx  = dtv * s_xc[i*64+d];
            sdt += dtv;
            #pragma unroll
            for(int s=0;s<DS;s++){
                float e = __expf(A[s]*dtv);
                Q[s] = fmaf(e, Q[s], dx*s_bc[i*16+s]);
            }
        }
    }
    int base = ((seq*NC+ck)*64 + d)*16;
    #pragma unroll
    for(int s=0;s<16;s+=4){
        float4 p;
        p.x = __expf(A[s  ]*sdt);
        p.y = __expf(A[s+1]*sdt);
        p.z = __expf(A[s+2]*sdt);
        p.w = __expf(A[s+3]*sdt);
        *(float4*)&g_P[base+s] = p;
        *(float4*)&g_Q[base+s] = make_float4(Q[s],Q[s+1],Q[s+2],Q[s+3]);
    }
}

// ---------------- K5: scan phase 2 — sequential across chunks ----------------
__global__ void k_scan2(){
    int idx = blockIdx.x*128 + threadIdx.x;     // SEQ*1024 = 16384
    int lane = idx & 1023; int seq = idx >> 10;
    float h = 0.f;
    int base = seq*NC*1024 + lane;
    #pragma unroll 8
    for(int c=0;c<NC;c++){
        g_hin[base + c*1024] = h;
        h = fmaf(g_P[base + c*1024], h, g_Q[base + c*1024]);
    }
}

// ---------------- K6: scan phase 3 — replay + y + gate fusion ----------------
__global__ void k_scan3(const float* __restrict__ A_log, const float* __restrict__ Dpar){
    __shared__ float s_dt[1024], s_xc[1024], s_z[1024], s_bc[256], s_cc[256];
    int seq=blockIdx.y, ck=blockIdx.x, g=seq>>2, d=threadIdx.x;
    float A[DS], h[DS];
    #pragma unroll
    for(int s=0;s<DS;s++) A[s] = -__expf(A_log[(g*64+d)*16+s]);
    int hb = ((seq*NC+ck)*64 + d)*16;
    #pragma unroll
    for(int s=0;s<16;s+=4){
        float4 v = *(const float4*)&g_hin[hb+s];
        h[s]=v.x; h[s+1]=v.y; h[s+2]=v.z; h[s+3]=v.w;
    }
    float Dp = Dpar[g*64+d];
    int tbase = ck*TC;
    for(int sub=0; sub<TC/16; sub++){
        int tb = tbase + sub*16;
        __syncthreads();
        for(int i=d;i<1024;i+=64){
            s_dt[i]=g_dt[(seq*Lseq+tb)*64 + i];
            s_xc[i]=g_xc[(seq*Lseq+tb)*64 + i];
            s_z [i]=g_z [(seq*Lseq+tb)*64 + i];
        }
        for(int i=d;i<256;i+=64){
            int t=i>>4, s=i&15;
            s_bc[i] = g_bc[(seq*Lseq+tb+t)*32 + s];
            s_cc[i] = g_bc[(seq*Lseq+tb+t)*32 + 16 + s];
        }
        __syncthreads();
        #pragma unroll 4
        for(int i=0;i<16;i++){
            float dtv = s_dt[i*64+d];
            float xcv = s_xc[i*64+d];
            float dx  = dtv*xcv;
            float y = 0.f;
            #pragma unroll
            for(int s=0;s<DS;s++){
                float e = __expf(A[s]*dtv);
                h[s] = fmaf(e, h[s], dx*s_bc[i*16+s]);
                y = fmaf(h[s], s_cc[i*16+s], y);
            }
            float zv = s_z[i*64+d];
            g_ym[(seq*Lseq+tb+i)*64 + d] = (y + Dp*xcv) * siluf(zv);
        }
    }
}

// ---------------- K7: out_proj(64->32) + skip + pvm_proj(32->32), 32 tok/block ----
__global__ void k_out(const float* __restrict__ W1, const float* __restrict__ W2,
                      const float* __restrict__ pb2, const float* __restrict__ skipv){
    __shared__ float sW1[64*32], sW2[32*32], spb[32], su[8*32], sym[32*64];
    int seq=blockIdx.y, g=seq>>2, b=seq&3, t0=blockIdx.x*32, tid=threadIdx.x;
    for(int i=tid;i<2048;i+=256) sW1[i]=W1[g*2048+i];
    for(int i=tid;i<1024;i+=256) sW2[i]=W2[g*1024+i];
    if(tid<32) spb[tid]=pb2[g*32+tid];
    for(int i=tid;i<2048;i+=256) sym[i]=g_ym[(seq*Lseq+t0)*64 + i];
    float skip = skipv[g];
    __syncthreads();
    int w = tid>>5, lane = tid&31;
    #pragma unroll
    for(int it=0; it<4; it++){
        int tl = it*8 + w;
        int t  = t0 + tl;
        float acc = 0.f;
        #pragma unroll 8
        for(int k=0;k<64;k++) acc = fmaf(sym[tl*64+k], sW1[k*32+lane], acc);
        float u = acc + skip * g_xn2[(seq*Lseq+t)*32 + lane];
        su[w*32+lane] = u;
        __syncwarp();
        float acc2 = spb[lane];
        #pragma unroll 8
        for(int n=0;n<32;n++) acc2 = fmaf(su[w*32+n], sW2[n*32+lane], acc2);
        g_zc[(b*Lseq+t)*128 + g*32 + lane] = acc2;
        __syncwarp();
    }
}

// ---------------- K8: final proj (128x128) + BN + exact GELU ----------------
__global__ void k_final(const float* __restrict__ pb2, const float* __restrict__ bg,
                        const float* __restrict__ bb, const float* __restrict__ bm,
                        const float* __restrict__ bv, float* __restrict__ out){
    __shared__ float st[32*128];
    int b = blockIdx.y, l0 = blockIdx.x*32, o = threadIdx.x;
    for(int i=o;i<4096;i+=128) st[i] = g_zc[(b*Lseq+l0)*128 + i];
    float scale = bg[o]*rsqrtf(bv[o]+EPSf);
    float c0 = (pb2[o]-bm[o])*scale + bb[o];
    __syncthreads();
    float acc[32];
    #pragma unroll
    for(int t=0;t<32;t++) acc[t]=0.f;
    #pragma unroll 4
    for(int c=0;c<128;c++){
        float w = g_pwt[c*128+o];
        #pragma unroll
        for(int t=0;t<32;t++) acc[t] = fmaf(st[t*128+c], w, acc[t]);
    }
    __syncthreads();
    #pragma unroll
    for(int t=0;t<32;t++){
        float v = fmaf(acc[t], scale, c0);
        st[o*32+t] = 0.5f*v*(1.f + erff(v*0.70710678118654752f));
    }
    __syncthreads();
    for(int i=o;i<4096;i+=128){
        int oo = i>>5, li = i&31;
        out[(b*128+oo)*Lseq + l0 + li] = st[i];
    }
}

// ---------------- launch ----------------
extern "C" void kernel_launch(void* const* d_in, const int* in_sizes, int n_in,
                              void* d_out, int out_size){
    const float* x         = (const float*)d_in[0];
    const float* ln_g      = (const float*)d_in[1];
    const float* ln_b      = (const float*)d_in[2];
    const float* pvm_ln_g  = (const float*)d_in[3];
    const float* pvm_ln_b  = (const float*)d_in[4];
    const float* in_proj_w = (const float*)d_in[5];
    const float* conv_w    = (const float*)d_in[6];
    const float* conv_b    = (const float*)d_in[7];
    const float* x_proj_w  = (const float*)d_in[8];
    const float* dt_proj_w = (const float*)d_in[9];
    const float* dt_bias   = (const float*)d_in[10];
    const float* A_log     = (const float*)d_in[11];
    const float* D_param   = (const float*)d_in[12];
    const float* out_proj_w= (const float*)d_in[13];
    const float* skip_scale= (const float*)d_in[14];
    const float* pvm_proj_w= (const float*)d_in[15];
    const float* pvm_proj_b= (const float*)d_in[16];
    const float* proj_w    = (const float*)d_in[17];
    const float* proj_b    = (const float*)d_in[18];
    const float* bn_g      = (const float*)d_in[19];
    const float* bn_b      = (const float*)d_in[20];
    const float* bn_mean   = (const float*)d_in[21];
    const float* bn_var    = (const float*)d_in[22];
    float* out = (float*)d_out;

    k_tr    <<<64, 256>>>(proj_w);
    k_ln    <<<dim3(128,4), 256>>>(x, ln_g, ln_b, pvm_ln_g, pvm_ln_b);
    k_inconv<<<dim3(128,16), 128>>>(in_proj_w, conv_w, conv_b);
    k_xproj <<<dim3(32,16), 128>>>(x_proj_w, dt_proj_w, dt_bias);
    k_scan1 <<<dim3(NC,16), 64>>>(A_log);
    k_scan2 <<<128, 128>>>();
    k_scan3 <<<dim3(NC,16), 64>>>(A_log, D_param);
    k_out   <<<dim3(128,16), 256>>>(out_proj_w, pvm_proj_w, pvm_proj_b, skip_scale);
    k_final <<<dim3(128,4), 128>>>(proj_b, bn_g, bn_b, bn_mean, bn_var, out);
}